// round 11
// baseline (speedup 1.0000x reference)
#include <cuda_runtime.h>
#include <math.h>
#include <stdint.h>

#define BB 4
#define TT 2048
#define CC 1024
#define HH 16
#define HD 64
#define MM (BB*TT)          // 8192 rows
#define NQKV (3*CC)         // 3072

// Scratch (device globals; allocation-free per harness rules)
__device__ float g_xr[(size_t)MM * CC];      // x rounded to tf32
__device__ float g_q[(size_t)MM * CC];       // [B,H,T,hd] tf32
__device__ float g_k[(size_t)MM * CC];       // [B,H,T,hd] tf32
__device__ float g_v[(size_t)MM * CC];       // [B,H,T,hd] tf32
__device__ float g_att[(size_t)MM * CC];     // [B,T,C] tf32
__device__ float g_wqkvT[(size_t)NQKV * CC]; // W_qkv^T [3072][1024], tf32
__device__ float g_woutT[(size_t)CC * CC];   // W_out^T [1024][1024], tf32

// ---------------------------------------------------------------------------
// Helpers
// ---------------------------------------------------------------------------
__device__ __forceinline__ float cvt_tf32(float x) {
    uint32_t r;
    asm("cvt.rna.tf32.f32 %0, %1;" : "=r"(r) : "f"(x));
    return __uint_as_float(r);
}

#define LDSM_X4(r0, r1, r2, r3, addr)                                         \
    asm volatile("ldmatrix.sync.aligned.m8n8.x4.shared.b16 {%0,%1,%2,%3}, [%4];" \
                 : "=r"(r0), "=r"(r1), "=r"(r2), "=r"(r3) : "r"(addr))

#define MMA_TF32(d, a, b)                                                     \
    asm volatile("mma.sync.aligned.m16n8k8.row.col.f32.tf32.tf32.f32 "        \
                 "{%0,%1,%2,%3}, {%4,%5,%6,%7}, {%8,%9}, {%0,%1,%2,%3};"      \
                 : "+f"(d[0]), "+f"(d[1]), "+f"(d[2]), "+f"(d[3])             \
                 : "r"(a[0]), "r"(a[1]), "r"(a[2]), "r"(a[3]),                \
                   "r"(b[0]), "r"(b[1]))

#define CP_ASYNC16(dst, src)                                                  \
    asm volatile("cp.async.cg.shared.global [%0], [%1], 16;"                  \
                 :: "r"(dst), "l"(src))
#define CP_COMMIT() asm volatile("cp.async.commit_group;")
#define CP_WAIT(n)  asm volatile("cp.async.wait_group %0;" :: "n"(n))

// ---------------------------------------------------------------------------
// Elementwise tf32 rounding of x.
// ---------------------------------------------------------------------------
__global__ __launch_bounds__(256) void round_x_kernel(const float* __restrict__ x)
{
    size_t i = ((size_t)blockIdx.x * 256 + threadIdx.x) * 4;
    float4 v = *(const float4*)&x[i];
    v.x = cvt_tf32(v.x); v.y = cvt_tf32(v.y);
    v.z = cvt_tf32(v.z); v.w = cvt_tf32(v.w);
    *(float4*)&g_xr[i] = v;
}

// ---------------------------------------------------------------------------
// Transpose weights [K][N] -> [N][K] with tf32 rounding.
// ---------------------------------------------------------------------------
__global__ __launch_bounds__(256) void transpose_tf32_kernel(
    const float* __restrict__ W, float* __restrict__ Wt, int K, int N)
{
    __shared__ float tile[32][33];
    int n0 = blockIdx.x * 32, k0 = blockIdx.y * 32;
    int tx = threadIdx.x & 31, ty = threadIdx.x >> 5;
#pragma unroll
    for (int i = 0; i < 32; i += 8)
        tile[ty + i][tx] = W[(size_t)(k0 + ty + i) * N + n0 + tx];
    __syncthreads();
#pragma unroll
    for (int i = 0; i < 32; i += 8)
        Wt[(size_t)(n0 + ty + i) * K + k0 + tx] = cvt_tf32(tile[tx][ty + i]);
}

// ---------------------------------------------------------------------------
// TF32 tensor-core GEMM, 3-stage cp.async ring, ONE __syncthreads per k-iter.
// ROPE=0: C[M,N] = A @ Bt^T + bias  (plain, used for out projection)
// ROPE=1: QKV projection: epilogue applies bias + RoPE + head split, writing
//         tf32-rounded g_q/g_k/g_v in [B,H,T,hd]; C unused.
// ---------------------------------------------------------------------------
#define GBM 128
#define GBN 128
#define GBK 32
#define GPAD 36
#define NSTAGE 3
#define GEMM_SMEM (NSTAGE * (GBM + GBN) * GPAD * 4)

template <int ROPE>
__global__ __launch_bounds__(256, 2) void tf32_gemm(
    const float* __restrict__ A, const float* __restrict__ Bt,
    const float* __restrict__ bias, float* __restrict__ C,
    int Nd, int Kd)
{
    extern __shared__ float smem[];
    // Layout per stage: A tile [GBM*GPAD], then B tile [GBN*GPAD].
    int tid  = threadIdx.x;
    int warp = tid >> 5, lane = tid & 31;
    int wm   = warp >> 1;
    int wn   = warp & 1;
    int bm   = blockIdx.y * GBM, bn = blockIdx.x * GBN;

    float acc[2][8][4];
#pragma unroll
    for (int mi = 0; mi < 2; mi++)
#pragma unroll
        for (int ni = 0; ni < 8; ni++)
#pragma unroll
            for (int c = 0; c < 4; c++) acc[mi][ni][c] = 0.f;

    int j = lane >> 3;
    int lrow = lane & 7;
    int a_row = ((j & 1) << 3) + lrow;
    int a_col = (j >> 1) << 2;
    int b_row = ((j >> 1) << 3) + lrow;
    int b_col = (j & 1) << 2;

    int cr = tid >> 3;             // 0..31 base row
    int ccq = (tid & 7) << 2;      // col (float4)

    const int STF = (GBM + GBN) * GPAD;      // floats per stage
    uint32_t sA[NSTAGE], sB[NSTAGE];
#pragma unroll
    for (int bf = 0; bf < NSTAGE; bf++) {
        sA[bf] = (uint32_t)__cvta_generic_to_shared(&smem[bf * STF]);
        sB[bf] = sA[bf] + GBM * GPAD * 4;
    }

#define GEMM_ISSUE(buf, k0)                                                   \
    {                                                                         \
        _Pragma("unroll")                                                     \
        for (int it = 0; it < 4; it++) {                                      \
            int r = cr + it * 32;                                             \
            uint32_t da = sA[buf] + (r * GPAD + ccq) * 4;                     \
            const float* pa = &A[(size_t)(bm + r) * Kd + (k0) + ccq];         \
            CP_ASYNC16(da, pa);                                               \
            uint32_t db = sB[buf] + (r * GPAD + ccq) * 4;                     \
            const float* pb = &Bt[(size_t)(bn + r) * Kd + (k0) + ccq];        \
            CP_ASYNC16(db, pb);                                               \
        }                                                                     \
        CP_COMMIT();                                                          \
    }

    int iters = Kd / GBK;
    GEMM_ISSUE(0, 0);
    GEMM_ISSUE(1, GBK);

    for (int i = 0; i < iters; i++) {
        if (i < iters - 1) { CP_WAIT(1); } else { CP_WAIT(0); }
        __syncthreads();     // stage i visible; all warps done with stage i-1

        if (i + 2 < iters) {
            int nb = (i + 2) % NSTAGE;
            GEMM_ISSUE(nb, (i + 2) * GBK);
        }

        int cbuf = i % NSTAGE;
        const float* As = &smem[cbuf * STF];
        const float* Bs = As + GBM * GPAD;

#pragma unroll
        for (int ks = 0; ks < 4; ks++) {
            int kc = ks * 8;
            uint32_t afr[2][4];
#pragma unroll
            for (int mi = 0; mi < 2; mi++) {
                int mr = wm * 32 + mi * 16;
                uint32_t addr = (uint32_t)__cvta_generic_to_shared(
                    &As[(mr + a_row) * GPAD + kc + a_col]);
                LDSM_X4(afr[mi][0], afr[mi][1], afr[mi][2], afr[mi][3], addr);
            }
            uint32_t bfr[8][2];
#pragma unroll
            for (int np = 0; np < 4; np++) {
                int nb2 = wn * 64 + np * 16;
                uint32_t addr = (uint32_t)__cvta_generic_to_shared(
                    &Bs[(nb2 + b_row) * GPAD + kc + b_col]);
                LDSM_X4(bfr[2 * np][0], bfr[2 * np][1],
                        bfr[2 * np + 1][0], bfr[2 * np + 1][1], addr);
            }
#pragma unroll
            for (int mi = 0; mi < 2; mi++)
#pragma unroll
                for (int ni = 0; ni < 8; ni++)
                    MMA_TF32(acc[mi][ni], afr[mi], bfr[ni]);
        }
        // no trailing barrier: next iteration's single barrier covers reuse
    }

    int g = lane >> 2, tq = lane & 3;

    if (ROPE) {
        // Epilogue: bias + RoPE + head split, write [B,H,T,hd] tf32.
        int n64 = bn + wn * 64;          // this warp's 64-col block
        int sel = n64 >> 10;             // 0=q, 1=k, 2=v
        int h   = (n64 >> 6) & (HH - 1);
        float* dst = (sel == 0) ? g_q : (sel == 1) ? g_k : g_v;

        if (sel == 2) {
#pragma unroll
            for (int mi = 0; mi < 2; mi++) {
#pragma unroll
                for (int half = 0; half < 2; half++) {
                    int row = bm + wm * 32 + mi * 16 + g + half * 8;
                    int t = row & (TT - 1), b = row >> 11;
                    float* o = dst + ((size_t)((b * HH + h) * TT + t)) * HD;
#pragma unroll
                    for (int ni = 0; ni < 8; ni++) {
                        int dl = ni * 8 + tq * 2;
                        float2 val;
                        val.x = cvt_tf32(acc[mi][ni][half * 2]     + bias[n64 + dl]);
                        val.y = cvt_tf32(acc[mi][ni][half * 2 + 1] + bias[n64 + dl + 1]);
                        *(float2*)&o[dl] = val;
                    }
                }
            }
        } else {
            float invf[8];
#pragma unroll
            for (int ni = 0; ni < 4; ni++)
#pragma unroll
                for (int c = 0; c < 2; c++)
                    invf[ni * 2 + c] =
                        exp2f(-(float)(ni * 8 + tq * 2 + c) * 0.4152410118609203f);
#pragma unroll
            for (int mi = 0; mi < 2; mi++) {
#pragma unroll
                for (int half = 0; half < 2; half++) {
                    int row = bm + wm * 32 + mi * 16 + g + half * 8;
                    int t = row & (TT - 1), b = row >> 11;
                    float* o = dst + ((size_t)((b * HH + h) * TT + t)) * HD;
                    float tf = (float)t;
#pragma unroll
                    for (int ni = 0; ni < 4; ni++) {
#pragma unroll
                        for (int c = 0; c < 2; c++) {
                            int dl = ni * 8 + tq * 2 + c;
                            float v1 = acc[mi][ni][half * 2 + c]     + bias[n64 + dl];
                            float v2 = acc[mi][ni + 4][half * 2 + c] + bias[n64 + dl + 32];
                            float s, cs;
                            sincosf(tf * invf[ni * 2 + c], &s, &cs);
                            o[dl]      = cvt_tf32(v1 * cs - v2 * s);
                            o[dl + 32] = cvt_tf32(v2 * cs + v1 * s);
                        }
                    }
                }
            }
        }
    } else {
#pragma unroll
        for (int ni = 0; ni < 8; ni++) {
            int col = bn + wn * 64 + ni * 8 + tq * 2;
            float b0 = bias[col], b1 = bias[col + 1];
#pragma unroll
            for (int mi = 0; mi < 2; mi++) {
                int row = bm + wm * 32 + mi * 16 + g;
                float2 lo = make_float2(acc[mi][ni][0] + b0, acc[mi][ni][1] + b1);
                float2 hi = make_float2(acc[mi][ni][2] + b0, acc[mi][ni][3] + b1);
                *(float2*)&C[(size_t)row * Nd + col]       = lo;
                *(float2*)&C[(size_t)(row + 8) * Nd + col] = hi;
            }
        }
    }
}

// ---------------------------------------------------------------------------
// Flash attention with TF32 mma.sync + 2-stage cp.async K/V pipeline.
// CTA = one (b,h) x 128-row Q tile; 8 warps x 16 rows; KV tiles of 64.
// V kept row-major; P@V B-fragment = two conflict-free LDS.32.
// Q/K/V pre-rounded to tf32 by the QKV GEMM rope epilogue.
// ---------------------------------------------------------------------------
#define AP 68
#define ATTN_SMEM ((128 * AP + 4 * 64 * AP) * 4)

__global__ __launch_bounds__(256, 2) void flash_attn_mma()
{
    extern __shared__ float sm[];
    float* sQ = sm;                      // [128][AP]
    float* sK = sm + 128 * AP;           // [2][64][AP]
    float* sV = sK + 2 * 64 * AP;        // [2][64][AP]

    int bh = blockIdx.y;
    int qt = (int)gridDim.x - 1 - (int)blockIdx.x;   // heavy tiles first
    int tid = threadIdx.x;
    int warp = tid >> 5, lane = tid & 31;
    int g = lane >> 2, q = lane & 3;

    const float* Qh = g_q + (size_t)bh * TT * HD;
    const float* Kh = g_k + (size_t)bh * TT * HD;
    const float* Vh = g_v + (size_t)bh * TT * HD;

    uint32_t uQ = (uint32_t)__cvta_generic_to_shared(sQ);
    uint32_t uK = (uint32_t)__cvta_generic_to_shared(sK);
    uint32_t uV = (uint32_t)__cvta_generic_to_shared(sV);

    int jm = lane >> 3, lrow = lane & 7;
    int a_row = ((jm & 1) << 3) + lrow, a_col = (jm >> 1) << 2;
    int b_row = ((jm >> 1) << 3) + lrow, b_col = (jm & 1) << 2;

    // Prologue: Q (128 rows x 16 chunks = 2048) + KV stage 0 (1024 each).
#pragma unroll
    for (int it = 0; it < 8; it++) {
        int slot = tid + it * 256;
        int r = slot >> 4, c4 = (slot & 15) << 2;
        CP_ASYNC16(uQ + (r * AP + c4) * 4,
                   &Qh[(size_t)(qt * 128 + r) * HD + c4]);
    }
#pragma unroll
    for (int it = 0; it < 4; it++) {
        int slot = tid + it * 256;
        int r = slot >> 4, c4 = (slot & 15) << 2;
        CP_ASYNC16(uK + (r * AP + c4) * 4, &Kh[(size_t)r * HD + c4]);
        CP_ASYNC16(uV + (r * AP + c4) * 4, &Vh[(size_t)r * HD + c4]);
    }
    CP_COMMIT();

    float m0 = -1e30f, m1 = -1e30f, l0 = 0.f, l1 = 0.f;
    float oacc[8][4];
#pragma unroll
    for (int ni = 0; ni < 8; ni++)
#pragma unroll
        for (int c = 0; c < 4; c++) oacc[ni][c] = 0.f;

    int row0 = qt * 128 + warp * 16 + g;
    int row1 = row0 + 8;

    int ktmax = 2 * qt + 1;
    for (int kt = 0; kt <= ktmax; kt++) {
        if (kt > 0) __syncthreads();   // readers of the stage we overwrite are done
        if (kt < ktmax) {
            int ns = (kt + 1) & 1;
            int kb2 = (kt + 1) * 64;
            uint32_t base = (uint32_t)(ns * 64 * AP) * 4;
#pragma unroll
            for (int it = 0; it < 4; it++) {
                int slot = tid + it * 256;
                int r = slot >> 4, c4 = (slot & 15) << 2;
                CP_ASYNC16(uK + base + (r * AP + c4) * 4,
                           &Kh[(size_t)(kb2 + r) * HD + c4]);
                CP_ASYNC16(uV + base + (r * AP + c4) * 4,
                           &Vh[(size_t)(kb2 + r) * HD + c4]);
            }
            CP_COMMIT();
            CP_WAIT(1);
        } else {
            CP_WAIT(0);
        }
        __syncthreads();

        int s = kt & 1;
        int kb = kt * 64;
        const float* sKs = sK + s * 64 * AP;
        const float* sVs = sV + s * 64 * AP;

        // S = Q @ K^T (warp: 16 x 64)
        float sf[8][4];
#pragma unroll
        for (int ni = 0; ni < 8; ni++)
#pragma unroll
            for (int c = 0; c < 4; c++) sf[ni][c] = 0.f;

#pragma unroll
        for (int kc8 = 0; kc8 < 8; kc8++) {
            int kc = kc8 * 8;
            uint32_t afr[4];
            uint32_t aad = (uint32_t)__cvta_generic_to_shared(
                &sQ[(warp * 16 + a_row) * AP + kc + a_col]);
            LDSM_X4(afr[0], afr[1], afr[2], afr[3], aad);
            uint32_t bfr[8][2];
#pragma unroll
            for (int np = 0; np < 4; np++) {
                uint32_t bad = (uint32_t)__cvta_generic_to_shared(
                    &sKs[(np * 16 + b_row) * AP + kc + b_col]);
                LDSM_X4(bfr[2 * np][0], bfr[2 * np][1],
                        bfr[2 * np + 1][0], bfr[2 * np + 1][1], bad);
            }
#pragma unroll
            for (int ni = 0; ni < 8; ni++)
                MMA_TF32(sf[ni], afr, bfr[ni]);
        }

        // Online softmax on fragments
        bool maskt = (kt >= 2 * qt);
        float rmax0 = -1e30f, rmax1 = -1e30f;
#pragma unroll
        for (int ni = 0; ni < 8; ni++) {
            sf[ni][0] *= 0.125f; sf[ni][1] *= 0.125f;
            sf[ni][2] *= 0.125f; sf[ni][3] *= 0.125f;
            if (maskt) {
                int c0 = kb + ni * 8 + 2 * q, c1 = c0 + 1;
                if (c0 > row0) sf[ni][0] = -1e30f;
                if (c1 > row0) sf[ni][1] = -1e30f;
                if (c0 > row1) sf[ni][2] = -1e30f;
                if (c1 > row1) sf[ni][3] = -1e30f;
            }
            rmax0 = fmaxf(rmax0, fmaxf(sf[ni][0], sf[ni][1]));
            rmax1 = fmaxf(rmax1, fmaxf(sf[ni][2], sf[ni][3]));
        }
        rmax0 = fmaxf(rmax0, __shfl_xor_sync(0xffffffffu, rmax0, 1));
        rmax0 = fmaxf(rmax0, __shfl_xor_sync(0xffffffffu, rmax0, 2));
        rmax1 = fmaxf(rmax1, __shfl_xor_sync(0xffffffffu, rmax1, 1));
        rmax1 = fmaxf(rmax1, __shfl_xor_sync(0xffffffffu, rmax1, 2));

        float mn0 = fmaxf(m0, rmax0), mn1 = fmaxf(m1, rmax1);
        float al0 = __expf(m0 - mn0), al1 = __expf(m1 - mn1);
        m0 = mn0; m1 = mn1;

        float rs0 = 0.f, rs1 = 0.f;
#pragma unroll
        for (int ni = 0; ni < 8; ni++) {
            float p0 = cvt_tf32(__expf(sf[ni][0] - mn0));
            float p1 = cvt_tf32(__expf(sf[ni][1] - mn0));
            float p2 = cvt_tf32(__expf(sf[ni][2] - mn1));
            float p3 = cvt_tf32(__expf(sf[ni][3] - mn1));
            sf[ni][0] = p0; sf[ni][1] = p1; sf[ni][2] = p2; sf[ni][3] = p3;
            rs0 += p0 + p1;
            rs1 += p2 + p3;
        }
        rs0 += __shfl_xor_sync(0xffffffffu, rs0, 1);
        rs0 += __shfl_xor_sync(0xffffffffu, rs0, 2);
        rs1 += __shfl_xor_sync(0xffffffffu, rs1, 1);
        rs1 += __shfl_xor_sync(0xffffffffu, rs1, 2);
        l0 = l0 * al0 + rs0;
        l1 = l1 * al1 + rs1;
#pragma unroll
        for (int ni = 0; ni < 8; ni++) {
            oacc[ni][0] *= al0; oacc[ni][1] *= al0;
            oacc[ni][2] *= al1; oacc[ni][3] *= al1;
        }

        // O += P @ V (V row-major; B-frag = two LDS.32, conflict-free)
#pragma unroll
        for (int kc8 = 0; kc8 < 8; kc8++) {
            uint32_t a[4];
            a[0] = __float_as_uint(sf[kc8][0]);
            a[1] = __float_as_uint(sf[kc8][2]);
            a[2] = __float_as_uint(sf[kc8][1]);
            a[3] = __float_as_uint(sf[kc8][3]);
            int cb = kc8 * 8 + 2 * q;
            const float* v0 = &sVs[cb * AP];
            const float* v1 = &sVs[(cb + 1) * AP];
#pragma unroll
            for (int ni = 0; ni < 8; ni++) {
                int n = ni * 8 + g;
                uint32_t b[2];
                b[0] = __float_as_uint(v0[n]);
                b[1] = __float_as_uint(v1[n]);
                MMA_TF32(oacc[ni], a, b);
            }
        }
    }

    // Epilogue: normalize, tf32-round (feeds out-proj GEMM), write [B,T,C]
    float inv0 = 1.0f / l0, inv1 = 1.0f / l1;
    int b_ = bh >> 4, h = bh & 15;
    int trow0 = qt * 128 + warp * 16 + g;
#pragma unroll
    for (int ni = 0; ni < 8; ni++) {
        int col = h * HD + ni * 8 + 2 * q;
        float2 lo = make_float2(cvt_tf32(oacc[ni][0] * inv0),
                                cvt_tf32(oacc[ni][1] * inv0));
        float2 hi = make_float2(cvt_tf32(oacc[ni][2] * inv1),
                                cvt_tf32(oacc[ni][3] * inv1));
        *(float2*)&g_att[((size_t)(b_ * TT + trow0)) * CC + col]     = lo;
        *(float2*)&g_att[((size_t)(b_ * TT + trow0 + 8)) * CC + col] = hi;
    }
}

// ---------------------------------------------------------------------------
extern "C" void kernel_launch(void* const* d_in, const int* in_sizes, int n_in,
                              void* d_out, int out_size)
{
    const float* x     = (const float*)d_in[0];
    const float* W_qkv = (const float*)d_in[1];
    const float* b_qkv = (const float*)d_in[2];
    const float* W_out = (const float*)d_in[3];
    const float* b_out = (const float*)d_in[4];
    float* out = (float*)d_out;

    float *xr, *att, *wqkvT, *woutT;
    cudaGetSymbolAddress((void**)&xr,    g_xr);
    cudaGetSymbolAddress((void**)&att,   g_att);
    cudaGetSymbolAddress((void**)&wqkvT, g_wqkvT);
    cudaGetSymbolAddress((void**)&woutT, g_woutT);

    cudaFuncSetAttribute(tf32_gemm<0>,
                         cudaFuncAttributeMaxDynamicSharedMemorySize, GEMM_SMEM);
    cudaFuncSetAttribute(tf32_gemm<1>,
                         cudaFuncAttributeMaxDynamicSharedMemorySize, GEMM_SMEM);
    cudaFuncSetAttribute(flash_attn_mma,
                         cudaFuncAttributeMaxDynamicSharedMemorySize, ATTN_SMEM);

    // 0) Weight transposes (tf32) + x rounding
    transpose_tf32_kernel<<<dim3(NQKV / 32, CC / 32), 256>>>(W_qkv, wqkvT, CC, NQKV);
    transpose_tf32_kernel<<<dim3(CC / 32, CC / 32), 256>>>(W_out, woutT, CC, CC);
    round_x_kernel<<<(MM * CC) / (256 * 4), 256>>>(x);

    // 1) QKV projection + fused bias/RoPE/head-split epilogue
    tf32_gemm<1><<<dim3(NQKV / GBN, MM / GBM), 256, GEMM_SMEM>>>(
        xr, wqkvT, b_qkv, nullptr, NQKV, CC);

    // 2) Causal flash attention (pipelined K/V)
    flash_attn_mma<<<dim3(TT / 128, BB * HH), 256, ATTN_SMEM>>>();

    // 3) Output projection
    tf32_gemm<0><<<dim3(CC / GBN, MM / GBM), 256, GEMM_SMEM>>>(
        att, woutT, b_out, out, CC, CC);
}

// round 13
// speedup vs baseline: 1.3531x; 1.3531x over previous
#include <cuda_runtime.h>
#include <math.h>
#include <stdint.h>

#define BB 4
#define TT 2048
#define CC 1024
#define HH 16
#define HD 64
#define MM (BB*TT)          // 8192 rows
#define NQKV (3*CC)         // 3072

// Scratch (device globals; allocation-free per harness rules)
__device__ float g_xr[(size_t)MM * CC];      // x rounded to tf32
__device__ float g_q[(size_t)MM * CC];       // [B,H,T,hd] tf32
__device__ float g_k[(size_t)MM * CC];       // [B,H,T,hd] tf32
__device__ float g_v[(size_t)MM * CC];       // [B,H,T,hd] tf32
__device__ float g_att[(size_t)MM * CC];     // [B,T,C] tf32
__device__ float g_wqkvT[(size_t)NQKV * CC]; // W_qkv^T [3072][1024], tf32
__device__ float g_woutT[(size_t)CC * CC];   // W_out^T [1024][1024], tf32

// ---------------------------------------------------------------------------
// Helpers
// ---------------------------------------------------------------------------
__device__ __forceinline__ float cvt_tf32(float x) {
    uint32_t r;
    asm("cvt.rna.tf32.f32 %0, %1;" : "=r"(r) : "f"(x));
    return __uint_as_float(r);
}

#define LDSM_X4(r0, r1, r2, r3, addr)                                         \
    asm volatile("ldmatrix.sync.aligned.m8n8.x4.shared.b16 {%0,%1,%2,%3}, [%4];" \
                 : "=r"(r0), "=r"(r1), "=r"(r2), "=r"(r3) : "r"(addr))

#define MMA_TF32(d, a, b)                                                     \
    asm volatile("mma.sync.aligned.m16n8k8.row.col.f32.tf32.tf32.f32 "        \
                 "{%0,%1,%2,%3}, {%4,%5,%6,%7}, {%8,%9}, {%0,%1,%2,%3};"      \
                 : "+f"(d[0]), "+f"(d[1]), "+f"(d[2]), "+f"(d[3])             \
                 : "r"(a[0]), "r"(a[1]), "r"(a[2]), "r"(a[3]),                \
                   "r"(b[0]), "r"(b[1]))

#define CP_ASYNC16(dst, src)                                                  \
    asm volatile("cp.async.cg.shared.global [%0], [%1], 16;"                  \
                 :: "r"(dst), "l"(src))
#define CP_COMMIT() asm volatile("cp.async.commit_group;")
#define CP_WAIT(n)  asm volatile("cp.async.wait_group %0;" :: "n"(n))

// ---------------------------------------------------------------------------
// Elementwise tf32 rounding of x.
// ---------------------------------------------------------------------------
__global__ __launch_bounds__(256) void round_x_kernel(const float* __restrict__ x)
{
    size_t i = ((size_t)blockIdx.x * 256 + threadIdx.x) * 4;
    float4 v = *(const float4*)&x[i];
    v.x = cvt_tf32(v.x); v.y = cvt_tf32(v.y);
    v.z = cvt_tf32(v.z); v.w = cvt_tf32(v.w);
    *(float4*)&g_xr[i] = v;
}

// ---------------------------------------------------------------------------
// Transpose weights [K][N] -> [N][K] with tf32 rounding.
// ---------------------------------------------------------------------------
__global__ __launch_bounds__(256) void transpose_tf32_kernel(
    const float* __restrict__ W, float* __restrict__ Wt, int K, int N)
{
    __shared__ float tile[32][33];
    int n0 = blockIdx.x * 32, k0 = blockIdx.y * 32;
    int tx = threadIdx.x & 31, ty = threadIdx.x >> 5;
#pragma unroll
    for (int i = 0; i < 32; i += 8)
        tile[ty + i][tx] = W[(size_t)(k0 + ty + i) * N + n0 + tx];
    __syncthreads();
#pragma unroll
    for (int i = 0; i < 32; i += 8)
        Wt[(size_t)(n0 + ty + i) * K + k0 + tx] = cvt_tf32(tile[tx][ty + i]);
}

// ---------------------------------------------------------------------------
// TF32 tensor-core GEMM, 2-stage cp.async double buffer, GBK=64:
// 128 MMAs per warp between barriers (2x the R10 amortization).
// ROPE=0: C[M,N] = A @ Bt^T + bias  (plain, used for out projection)
// ROPE=1: QKV projection: epilogue applies bias + RoPE + head split, writing
//         tf32-rounded g_q/g_k/g_v in [B,H,T,hd]; C unused.
// ---------------------------------------------------------------------------
#define GBM 128
#define GBN 128
#define GBK 64
#define GPAD 68
#define GEMM_SMEM (2 * (GBM + GBN) * GPAD * 4)   // 139,264 B -> 1 CTA/SM

template <int ROPE>
__global__ __launch_bounds__(256, 1) void tf32_gemm(
    const float* __restrict__ A, const float* __restrict__ Bt,
    const float* __restrict__ bias, float* __restrict__ C,
    int Nd, int Kd)
{
    extern __shared__ float smem[];
    float* Asm = smem;                       // [2][GBM*GPAD]
    float* Bsm = smem + 2 * GBM * GPAD;      // [2][GBN*GPAD]

    int tid  = threadIdx.x;
    int warp = tid >> 5, lane = tid & 31;
    int wm   = warp >> 1;
    int wn   = warp & 1;
    int bm   = blockIdx.y * GBM, bn = blockIdx.x * GBN;

    float acc[2][8][4];
#pragma unroll
    for (int mi = 0; mi < 2; mi++)
#pragma unroll
        for (int ni = 0; ni < 8; ni++)
#pragma unroll
            for (int c = 0; c < 4; c++) acc[mi][ni][c] = 0.f;

    int j = lane >> 3;
    int lrow = lane & 7;
    int a_row = ((j & 1) << 3) + lrow;
    int a_col = (j >> 1) << 2;
    int b_row = ((j >> 1) << 3) + lrow;
    int b_col = (j & 1) << 2;

    uint32_t sA[2], sB[2];
#pragma unroll
    for (int bf = 0; bf < 2; bf++) {
        sA[bf] = (uint32_t)__cvta_generic_to_shared(&Asm[bf * GBM * GPAD]);
        sB[bf] = (uint32_t)__cvta_generic_to_shared(&Bsm[bf * GBN * GPAD]);
    }

    // 128 rows x 16 float4 chunks = 2048 slots per operand; 8 per thread.
#define GEMM_ISSUE(buf, k0)                                                   \
    {                                                                         \
        _Pragma("unroll")                                                     \
        for (int it = 0; it < 8; it++) {                                      \
            int slot = tid + it * 256;                                        \
            int r = slot >> 4, c4 = (slot & 15) << 2;                         \
            uint32_t da = sA[buf] + (r * GPAD + c4) * 4;                      \
            CP_ASYNC16(da, &A[(size_t)(bm + r) * Kd + (k0) + c4]);            \
            uint32_t db = sB[buf] + (r * GPAD + c4) * 4;                      \
            CP_ASYNC16(db, &Bt[(size_t)(bn + r) * Kd + (k0) + c4]);           \
        }                                                                     \
        CP_COMMIT();                                                          \
    }

    int iters = Kd / GBK;
    GEMM_ISSUE(0, 0);

    for (int i = 0; i < iters; i++) {
        if (i + 1 < iters) {
            GEMM_ISSUE((i + 1) & 1, (i + 1) * GBK);
            CP_WAIT(1);
        } else {
            CP_WAIT(0);
        }
        __syncthreads();

        const float* As = &Asm[(i & 1) * GBM * GPAD];
        const float* Bs = &Bsm[(i & 1) * GBN * GPAD];

#pragma unroll
        for (int ks = 0; ks < 8; ks++) {
            int kc = ks * 8;
            uint32_t afr[2][4];
#pragma unroll
            for (int mi = 0; mi < 2; mi++) {
                int mr = wm * 32 + mi * 16;
                uint32_t addr = (uint32_t)__cvta_generic_to_shared(
                    &As[(mr + a_row) * GPAD + kc + a_col]);
                LDSM_X4(afr[mi][0], afr[mi][1], afr[mi][2], afr[mi][3], addr);
            }
            uint32_t bfr[8][2];
#pragma unroll
            for (int np = 0; np < 4; np++) {
                int nb = wn * 64 + np * 16;
                uint32_t addr = (uint32_t)__cvta_generic_to_shared(
                    &Bs[(nb + b_row) * GPAD + kc + b_col]);
                LDSM_X4(bfr[2 * np][0], bfr[2 * np][1],
                        bfr[2 * np + 1][0], bfr[2 * np + 1][1], addr);
            }
#pragma unroll
            for (int mi = 0; mi < 2; mi++)
#pragma unroll
                for (int ni = 0; ni < 8; ni++)
                    MMA_TF32(acc[mi][ni], afr[mi], bfr[ni]);
        }
        __syncthreads();
    }

    int g = lane >> 2, tq = lane & 3;

    if (ROPE) {
        // Epilogue: bias + RoPE + head split, write [B,H,T,hd] tf32.
        int n64 = bn + wn * 64;          // this warp's 64-col block
        int sel = n64 >> 10;             // 0=q, 1=k, 2=v
        int h   = (n64 >> 6) & (HH - 1);
        float* dst = (sel == 0) ? g_q : (sel == 1) ? g_k : g_v;

        if (sel == 2) {
#pragma unroll
            for (int mi = 0; mi < 2; mi++) {
#pragma unroll
                for (int half = 0; half < 2; half++) {
                    int row = bm + wm * 32 + mi * 16 + g + half * 8;
                    int t = row & (TT - 1), b = row >> 11;
                    float* o = dst + ((size_t)((b * HH + h) * TT + t)) * HD;
#pragma unroll
                    for (int ni = 0; ni < 8; ni++) {
                        int dl = ni * 8 + tq * 2;
                        float2 val;
                        val.x = cvt_tf32(acc[mi][ni][half * 2]     + bias[n64 + dl]);
                        val.y = cvt_tf32(acc[mi][ni][half * 2 + 1] + bias[n64 + dl + 1]);
                        *(float2*)&o[dl] = val;
                    }
                }
            }
        } else {
            float invf[8];
#pragma unroll
            for (int ni = 0; ni < 4; ni++)
#pragma unroll
                for (int c = 0; c < 2; c++)
                    invf[ni * 2 + c] =
                        exp2f(-(float)(ni * 8 + tq * 2 + c) * 0.4152410118609203f);
#pragma unroll
            for (int mi = 0; mi < 2; mi++) {
#pragma unroll
                for (int half = 0; half < 2; half++) {
                    int row = bm + wm * 32 + mi * 16 + g + half * 8;
                    int t = row & (TT - 1), b = row >> 11;
                    float* o = dst + ((size_t)((b * HH + h) * TT + t)) * HD;
                    float tf = (float)t;
#pragma unroll
                    for (int ni = 0; ni < 4; ni++) {
#pragma unroll
                        for (int c = 0; c < 2; c++) {
                            int dl = ni * 8 + tq * 2 + c;
                            float v1 = acc[mi][ni][half * 2 + c]     + bias[n64 + dl];
                            float v2 = acc[mi][ni + 4][half * 2 + c] + bias[n64 + dl + 32];
                            float s, cs;
                            sincosf(tf * invf[ni * 2 + c], &s, &cs);
                            o[dl]      = cvt_tf32(v1 * cs - v2 * s);
                            o[dl + 32] = cvt_tf32(v2 * cs + v1 * s);
                        }
                    }
                }
            }
        }
    } else {
#pragma unroll
        for (int ni = 0; ni < 8; ni++) {
            int col = bn + wn * 64 + ni * 8 + tq * 2;
            float b0 = bias[col], b1 = bias[col + 1];
#pragma unroll
            for (int mi = 0; mi < 2; mi++) {
                int row = bm + wm * 32 + mi * 16 + g;
                float2 lo = make_float2(acc[mi][ni][0] + b0, acc[mi][ni][1] + b1);
                float2 hi = make_float2(acc[mi][ni][2] + b0, acc[mi][ni][3] + b1);
                *(float2*)&C[(size_t)row * Nd + col]       = lo;
                *(float2*)&C[(size_t)(row + 8) * Nd + col] = hi;
            }
        }
    }
}

// ---------------------------------------------------------------------------
// Flash attention with TF32 mma.sync + 2-stage cp.async K/V pipeline.
// (Unchanged from R10 — proven at ~273us, ~89% of mma.sync ceiling.)
// ---------------------------------------------------------------------------
#define AP 68
#define ATTN_SMEM ((128 * AP + 4 * 64 * AP) * 4)

__global__ __launch_bounds__(256, 2) void flash_attn_mma()
{
    extern __shared__ float sm[];
    float* sQ = sm;                      // [128][AP]
    float* sK = sm + 128 * AP;           // [2][64][AP]
    float* sV = sK + 2 * 64 * AP;        // [2][64][AP]

    int bh = blockIdx.y;
    int qt = (int)gridDim.x - 1 - (int)blockIdx.x;   // heavy tiles first
    int tid = threadIdx.x;
    int warp = tid >> 5, lane = tid & 31;
    int g = lane >> 2, q = lane & 3;

    const float* Qh = g_q + (size_t)bh * TT * HD;
    const float* Kh = g_k + (size_t)bh * TT * HD;
    const float* Vh = g_v + (size_t)bh * TT * HD;

    uint32_t uQ = (uint32_t)__cvta_generic_to_shared(sQ);
    uint32_t uK = (uint32_t)__cvta_generic_to_shared(sK);
    uint32_t uV = (uint32_t)__cvta_generic_to_shared(sV);

    int jm = lane >> 3, lrow = lane & 7;
    int a_row = ((jm & 1) << 3) + lrow, a_col = (jm >> 1) << 2;
    int b_row = ((jm >> 1) << 3) + lrow, b_col = (jm & 1) << 2;

    // Prologue: Q (128 rows x 16 chunks = 2048) + KV stage 0 (1024 each).
#pragma unroll
    for (int it = 0; it < 8; it++) {
        int slot = tid + it * 256;
        int r = slot >> 4, c4 = (slot & 15) << 2;
        CP_ASYNC16(uQ + (r * AP + c4) * 4,
                   &Qh[(size_t)(qt * 128 + r) * HD + c4]);
    }
#pragma unroll
    for (int it = 0; it < 4; it++) {
        int slot = tid + it * 256;
        int r = slot >> 4, c4 = (slot & 15) << 2;
        CP_ASYNC16(uK + (r * AP + c4) * 4, &Kh[(size_t)r * HD + c4]);
        CP_ASYNC16(uV + (r * AP + c4) * 4, &Vh[(size_t)r * HD + c4]);
    }
    CP_COMMIT();

    float m0 = -1e30f, m1 = -1e30f, l0 = 0.f, l1 = 0.f;
    float oacc[8][4];
#pragma unroll
    for (int ni = 0; ni < 8; ni++)
#pragma unroll
        for (int c = 0; c < 4; c++) oacc[ni][c] = 0.f;

    int row0 = qt * 128 + warp * 16 + g;
    int row1 = row0 + 8;

    int ktmax = 2 * qt + 1;
    for (int kt = 0; kt <= ktmax; kt++) {
        if (kt > 0) __syncthreads();   // readers of the stage we overwrite are done
        if (kt < ktmax) {
            int ns = (kt + 1) & 1;
            int kb2 = (kt + 1) * 64;
            uint32_t base = (uint32_t)(ns * 64 * AP) * 4;
#pragma unroll
            for (int it = 0; it < 4; it++) {
                int slot = tid + it * 256;
                int r = slot >> 4, c4 = (slot & 15) << 2;
                CP_ASYNC16(uK + base + (r * AP + c4) * 4,
                           &Kh[(size_t)(kb2 + r) * HD + c4]);
                CP_ASYNC16(uV + base + (r * AP + c4) * 4,
                           &Vh[(size_t)(kb2 + r) * HD + c4]);
            }
            CP_COMMIT();
            CP_WAIT(1);
        } else {
            CP_WAIT(0);
        }
        __syncthreads();

        int s = kt & 1;
        int kb = kt * 64;
        const float* sKs = sK + s * 64 * AP;
        const float* sVs = sV + s * 64 * AP;

        // S = Q @ K^T (warp: 16 x 64)
        float sf[8][4];
#pragma unroll
        for (int ni = 0; ni < 8; ni++)
#pragma unroll
            for (int c = 0; c < 4; c++) sf[ni][c] = 0.f;

#pragma unroll
        for (int kc8 = 0; kc8 < 8; kc8++) {
            int kc = kc8 * 8;
            uint32_t afr[4];
            uint32_t aad = (uint32_t)__cvta_generic_to_shared(
                &sQ[(warp * 16 + a_row) * AP + kc + a_col]);
            LDSM_X4(afr[0], afr[1], afr[2], afr[3], aad);
            uint32_t bfr[8][2];
#pragma unroll
            for (int np = 0; np < 4; np++) {
                uint32_t bad = (uint32_t)__cvta_generic_to_shared(
                    &sKs[(np * 16 + b_row) * AP + kc + b_col]);
                LDSM_X4(bfr[2 * np][0], bfr[2 * np][1],
                        bfr[2 * np + 1][0], bfr[2 * np + 1][1], bad);
            }
#pragma unroll
            for (int ni = 0; ni < 8; ni++)
                MMA_TF32(sf[ni], afr, bfr[ni]);
        }

        // Online softmax on fragments
        bool maskt = (kt >= 2 * qt);
        float rmax0 = -1e30f, rmax1 = -1e30f;
#pragma unroll
        for (int ni = 0; ni < 8; ni++) {
            sf[ni][0] *= 0.125f; sf[ni][1] *= 0.125f;
            sf[ni][2] *= 0.125f; sf[ni][3] *= 0.125f;
            if (maskt) {
                int c0 = kb + ni * 8 + 2 * q, c1 = c0 + 1;
                if (c0 > row0) sf[ni][0] = -1e30f;
                if (c1 > row0) sf[ni][1] = -1e30f;
                if (c0 > row1) sf[ni][2] = -1e30f;
                if (c1 > row1) sf[ni][3] = -1e30f;
            }
            rmax0 = fmaxf(rmax0, fmaxf(sf[ni][0], sf[ni][1]));
            rmax1 = fmaxf(rmax1, fmaxf(sf[ni][2], sf[ni][3]));
        }
        rmax0 = fmaxf(rmax0, __shfl_xor_sync(0xffffffffu, rmax0, 1));
        rmax0 = fmaxf(rmax0, __shfl_xor_sync(0xffffffffu, rmax0, 2));
        rmax1 = fmaxf(rmax1, __shfl_xor_sync(0xffffffffu, rmax1, 1));
        rmax1 = fmaxf(rmax1, __shfl_xor_sync(0xffffffffu, rmax1, 2));

        float mn0 = fmaxf(m0, rmax0), mn1 = fmaxf(m1, rmax1);
        float al0 = __expf(m0 - mn0), al1 = __expf(m1 - mn1);
        m0 = mn0; m1 = mn1;

        float rs0 = 0.f, rs1 = 0.f;
#pragma unroll
        for (int ni = 0; ni < 8; ni++) {
            float p0 = cvt_tf32(__expf(sf[ni][0] - mn0));
            float p1 = cvt_tf32(__expf(sf[ni][1] - mn0));
            float p2 = cvt_tf32(__expf(sf[ni][2] - mn1));
            float p3 = cvt_tf32(__expf(sf[ni][3] - mn1));
            sf[ni][0] = p0; sf[ni][1] = p1; sf[ni][2] = p2; sf[ni][3] = p3;
            rs0 += p0 + p1;
            rs1 += p2 + p3;
        }
        rs0 += __shfl_xor_sync(0xffffffffu, rs0, 1);
        rs0 += __shfl_xor_sync(0xffffffffu, rs0, 2);
        rs1 += __shfl_xor_sync(0xffffffffu, rs1, 1);
        rs1 += __shfl_xor_sync(0xffffffffu, rs1, 2);
        l0 = l0 * al0 + rs0;
        l1 = l1 * al1 + rs1;
#pragma unroll
        for (int ni = 0; ni < 8; ni++) {
            oacc[ni][0] *= al0; oacc[ni][1] *= al0;
            oacc[ni][2] *= al1; oacc[ni][3] *= al1;
        }

        // O += P @ V (V row-major; B-frag = two LDS.32, conflict-free)
#pragma unroll
        for (int kc8 = 0; kc8 < 8; kc8++) {
            uint32_t a[4];
            a[0] = __float_as_uint(sf[kc8][0]);
            a[1] = __float_as_uint(sf[kc8][2]);
            a[2] = __float_as_uint(sf[kc8][1]);
            a[3] = __float_as_uint(sf[kc8][3]);
            int cb = kc8 * 8 + 2 * q;
            const float* v0 = &sVs[cb * AP];
            const float* v1 = &sVs[(cb + 1) * AP];
#pragma unroll
            for (int ni = 0; ni < 8; ni++) {
                int n = ni * 8 + g;
                uint32_t b[2];
                b[0] = __float_as_uint(v0[n]);
                b[1] = __float_as_uint(v1[n]);
                MMA_TF32(oacc[ni], a, b);
            }
        }
    }

    // Epilogue: normalize, tf32-round (feeds out-proj GEMM), write [B,T,C]
    float inv0 = 1.0f / l0, inv1 = 1.0f / l1;
    int b_ = bh >> 4, h = bh & 15;
    int trow0 = qt * 128 + warp * 16 + g;
#pragma unroll
    for (int ni = 0; ni < 8; ni++) {
        int col = h * HD + ni * 8 + 2 * q;
        float2 lo = make_float2(cvt_tf32(oacc[ni][0] * inv0),
                                cvt_tf32(oacc[ni][1] * inv0));
        float2 hi = make_float2(cvt_tf32(oacc[ni][2] * inv1),
                                cvt_tf32(oacc[ni][3] * inv1));
        *(float2*)&g_att[((size_t)(b_ * TT + trow0)) * CC + col]     = lo;
        *(float2*)&g_att[((size_t)(b_ * TT + trow0 + 8)) * CC + col] = hi;
    }
}

// ---------------------------------------------------------------------------
extern "C" void kernel_launch(void* const* d_in, const int* in_sizes, int n_in,
                              void* d_out, int out_size)
{
    const float* x     = (const float*)d_in[0];
    const float* W_qkv = (const float*)d_in[1];
    const float* b_qkv = (const float*)d_in[2];
    const float* W_out = (const float*)d_in[3];
    const float* b_out = (const float*)d_in[4];
    float* out = (float*)d_out;

    float *xr, *att, *wqkvT, *woutT;
    cudaGetSymbolAddress((void**)&xr,    g_xr);
    cudaGetSymbolAddress((void**)&att,   g_att);
    cudaGetSymbolAddress((void**)&wqkvT, g_wqkvT);
    cudaGetSymbolAddress((void**)&woutT, g_woutT);

    cudaFuncSetAttribute(tf32_gemm<0>,
                         cudaFuncAttributeMaxDynamicSharedMemorySize, GEMM_SMEM);
    cudaFuncSetAttribute(tf32_gemm<1>,
                         cudaFuncAttributeMaxDynamicSharedMemorySize, GEMM_SMEM);
    cudaFuncSetAttribute(flash_attn_mma,
                         cudaFuncAttributeMaxDynamicSharedMemorySize, ATTN_SMEM);

    // 0) Weight transposes (tf32) + x rounding
    transpose_tf32_kernel<<<dim3(NQKV / 32, CC / 32), 256>>>(W_qkv, wqkvT, CC, NQKV);
    transpose_tf32_kernel<<<dim3(CC / 32, CC / 32), 256>>>(W_out, woutT, CC, CC);
    round_x_kernel<<<(MM * CC) / (256 * 4), 256>>>(x);

    // 1) QKV projection + fused bias/RoPE/head-split epilogue
    tf32_gemm<1><<<dim3(NQKV / GBN, MM / GBM), 256, GEMM_SMEM>>>(
        xr, wqkvT, b_qkv, nullptr, NQKV, CC);

    // 2) Causal flash attention (pipelined K/V)
    flash_attn_mma<<<dim3(TT / 128, BB * HH), 256, ATTN_SMEM>>>();

    // 3) Output projection
    tf32_gemm<0><<<dim3(CC / GBN, MM / GBM), 256, GEMM_SMEM>>>(
        att, woutT, b_out, out, CC, CC);
}

// round 15
// speedup vs baseline: 1.4253x; 1.0534x over previous
#include <cuda_runtime.h>
#include <math.h>
#include <stdint.h>

#define BB 4
#define TT 2048
#define CC 1024
#define HH 16
#define HD 64
#define MM (BB*TT)          // 8192 rows
#define NQKV (3*CC)         // 3072

// Scratch (device globals; allocation-free per harness rules)
__device__ float g_xr[(size_t)MM * CC];      // x rounded to tf32
__device__ float g_q[(size_t)MM * CC];       // [B,H,T,hd] tf32
__device__ float g_k[(size_t)MM * CC];       // [B,H,T,hd] tf32
__device__ float g_v[(size_t)MM * CC];       // [B,H,T,hd] tf32
__device__ float g_att[(size_t)MM * CC];     // [B,T,C] tf32
__device__ float g_wqkvT[(size_t)NQKV * CC]; // W_qkv^T [3072][1024], tf32
__device__ float g_woutT[(size_t)CC * CC];   // W_out^T [1024][1024], tf32

// ---------------------------------------------------------------------------
// Helpers
// ---------------------------------------------------------------------------
__device__ __forceinline__ float cvt_tf32(float x) {
    uint32_t r;
    asm("cvt.rna.tf32.f32 %0, %1;" : "=r"(r) : "f"(x));
    return __uint_as_float(r);
}

#define LDSM_X4(r0, r1, r2, r3, addr)                                         \
    asm volatile("ldmatrix.sync.aligned.m8n8.x4.shared.b16 {%0,%1,%2,%3}, [%4];" \
                 : "=r"(r0), "=r"(r1), "=r"(r2), "=r"(r3) : "r"(addr))

#define MMA_TF32(d, a, b)                                                     \
    asm volatile("mma.sync.aligned.m16n8k8.row.col.f32.tf32.tf32.f32 "        \
                 "{%0,%1,%2,%3}, {%4,%5,%6,%7}, {%8,%9}, {%0,%1,%2,%3};"      \
                 : "+f"(d[0]), "+f"(d[1]), "+f"(d[2]), "+f"(d[3])             \
                 : "r"(a[0]), "r"(a[1]), "r"(a[2]), "r"(a[3]),                \
                   "r"(b[0]), "r"(b[1]))

#define CP_ASYNC16(dst, src)                                                  \
    asm volatile("cp.async.cg.shared.global [%0], [%1], 16;"                  \
                 :: "r"(dst), "l"(src))
#define CP_COMMIT() asm volatile("cp.async.commit_group;")
#define CP_WAIT(n)  asm volatile("cp.async.wait_group %0;" :: "n"(n))

// ---------------------------------------------------------------------------
// Fused prologue: transpose W_qkv + transpose W_out (tf32) + round x (tf32).
// Block ranges: [0, 3072) -> W_qkv tiles, [3072, 4096) -> W_out tiles,
//               [4096, 12288) -> round_x chunks of 1024 floats.
// ---------------------------------------------------------------------------
__global__ __launch_bounds__(256) void prologue_kernel(
    const float* __restrict__ x,
    const float* __restrict__ W_qkv,
    const float* __restrict__ W_out)
{
    int bid = blockIdx.x;
    if (bid < 4096) {
        __shared__ float tile[32][33];
        const float* W;
        float* Wt;
        int n0, k0, K, N;
        if (bid < 3072) {
            W = W_qkv; Wt = g_wqkvT; K = CC; N = NQKV;
            n0 = (bid % 96) * 32; k0 = (bid / 96) * 32;
        } else {
            int id = bid - 3072;
            W = W_out; Wt = g_woutT; K = CC; N = CC;
            n0 = (id & 31) * 32; k0 = (id >> 5) * 32;
        }
        int tx = threadIdx.x & 31, ty = threadIdx.x >> 5;
#pragma unroll
        for (int i = 0; i < 32; i += 8)
            tile[ty + i][tx] = W[(size_t)(k0 + ty + i) * N + n0 + tx];
        __syncthreads();
#pragma unroll
        for (int i = 0; i < 32; i += 8)
            Wt[(size_t)(n0 + ty + i) * K + k0 + tx] = cvt_tf32(tile[tx][ty + i]);
    } else {
        size_t i = ((size_t)(bid - 4096) * 256 + threadIdx.x) * 4;
        float4 v = *(const float4*)&x[i];
        v.x = cvt_tf32(v.x); v.y = cvt_tf32(v.y);
        v.z = cvt_tf32(v.z); v.w = cvt_tf32(v.w);
        *(float4*)&g_xr[i] = v;
    }
}

// ---------------------------------------------------------------------------
// TF32 tensor-core GEMM, 2-stage cp.async double buffer (exact R10 config:
// GBK=32, GPAD=36, 2 CTAs/SM — the proven best operating point).
// ROPE=0: C[M,N] = A @ Bt^T + bias  (plain, used for out projection)
// ROPE=1: QKV projection: epilogue applies bias + RoPE + head split, writing
//         tf32-rounded g_q/g_k/g_v in [B,H,T,hd]; C unused.
// ---------------------------------------------------------------------------
#define GBM 128
#define GBN 128
#define GBK 32
#define GPAD 36
#define GEMM_SMEM (2 * (GBM + GBN) * GPAD * 4)

template <int ROPE>
__global__ __launch_bounds__(256, 2) void tf32_gemm(
    const float* __restrict__ A, const float* __restrict__ Bt,
    const float* __restrict__ bias, float* __restrict__ C,
    int Nd, int Kd)
{
    extern __shared__ float smem[];
    float* Asm = smem;                       // [2][GBM*GPAD]
    float* Bsm = smem + 2 * GBM * GPAD;      // [2][GBN*GPAD]

    int tid  = threadIdx.x;
    int warp = tid >> 5, lane = tid & 31;
    int wm   = warp >> 1;
    int wn   = warp & 1;
    int bm   = blockIdx.y * GBM, bn = blockIdx.x * GBN;

    float acc[2][8][4];
#pragma unroll
    for (int mi = 0; mi < 2; mi++)
#pragma unroll
        for (int ni = 0; ni < 8; ni++)
#pragma unroll
            for (int c = 0; c < 4; c++) acc[mi][ni][c] = 0.f;

    int j = lane >> 3;
    int lrow = lane & 7;
    int a_row = ((j & 1) << 3) + lrow;
    int a_col = (j >> 1) << 2;
    int b_row = ((j >> 1) << 3) + lrow;
    int b_col = (j & 1) << 2;

    int cr = tid >> 3;             // 0..31 base row
    int ccq = (tid & 7) << 2;      // col (float4)

    uint32_t sA[2], sB[2];
#pragma unroll
    for (int bf = 0; bf < 2; bf++) {
        sA[bf] = (uint32_t)__cvta_generic_to_shared(&Asm[bf * GBM * GPAD]);
        sB[bf] = (uint32_t)__cvta_generic_to_shared(&Bsm[bf * GBN * GPAD]);
    }

#define GEMM_ISSUE(buf, k0)                                                   \
    {                                                                         \
        _Pragma("unroll")                                                     \
        for (int it = 0; it < 4; it++) {                                      \
            int r = cr + it * 32;                                             \
            uint32_t da = sA[buf] + (r * GPAD + ccq) * 4;                     \
            const float* pa = &A[(size_t)(bm + r) * Kd + (k0) + ccq];         \
            CP_ASYNC16(da, pa);                                               \
            uint32_t db = sB[buf] + (r * GPAD + ccq) * 4;                     \
            const float* pb = &Bt[(size_t)(bn + r) * Kd + (k0) + ccq];        \
            CP_ASYNC16(db, pb);                                               \
        }                                                                     \
        CP_COMMIT();                                                          \
    }

    int iters = Kd / GBK;
    GEMM_ISSUE(0, 0);

    for (int i = 0; i < iters; i++) {
        if (i + 1 < iters) {
            GEMM_ISSUE((i + 1) & 1, (i + 1) * GBK);
            CP_WAIT(1);
        } else {
            CP_WAIT(0);
        }
        __syncthreads();

        const float* As = &Asm[(i & 1) * GBM * GPAD];
        const float* Bs = &Bsm[(i & 1) * GBN * GPAD];

#pragma unroll
        for (int ks = 0; ks < 4; ks++) {
            int kc = ks * 8;
            uint32_t afr[2][4];
#pragma unroll
            for (int mi = 0; mi < 2; mi++) {
                int mr = wm * 32 + mi * 16;
                uint32_t addr = (uint32_t)__cvta_generic_to_shared(
                    &As[(mr + a_row) * GPAD + kc + a_col]);
                LDSM_X4(afr[mi][0], afr[mi][1], afr[mi][2], afr[mi][3], addr);
            }
            uint32_t bfr[8][2];
#pragma unroll
            for (int np = 0; np < 4; np++) {
                int nb = wn * 64 + np * 16;
                uint32_t addr = (uint32_t)__cvta_generic_to_shared(
                    &Bs[(nb + b_row) * GPAD + kc + b_col]);
                LDSM_X4(bfr[2 * np][0], bfr[2 * np][1],
                        bfr[2 * np + 1][0], bfr[2 * np + 1][1], addr);
            }
#pragma unroll
            for (int mi = 0; mi < 2; mi++)
#pragma unroll
                for (int ni = 0; ni < 8; ni++)
                    MMA_TF32(acc[mi][ni], afr[mi], bfr[ni]);
        }
        __syncthreads();
    }

    int g = lane >> 2, tq = lane & 3;

    if (ROPE) {
        // Epilogue: bias + RoPE + head split, write [B,H,T,hd] tf32.
        int n64 = bn + wn * 64;          // this warp's 64-col block
        int sel = n64 >> 10;             // 0=q, 1=k, 2=v
        int h   = (n64 >> 6) & (HH - 1);
        float* dst = (sel == 0) ? g_q : (sel == 1) ? g_k : g_v;

        if (sel == 2) {
#pragma unroll
            for (int mi = 0; mi < 2; mi++) {
#pragma unroll
                for (int half = 0; half < 2; half++) {
                    int row = bm + wm * 32 + mi * 16 + g + half * 8;
                    int t = row & (TT - 1), b = row >> 11;
                    float* o = dst + ((size_t)((b * HH + h) * TT + t)) * HD;
#pragma unroll
                    for (int ni = 0; ni < 8; ni++) {
                        int dl = ni * 8 + tq * 2;
                        float2 val;
                        val.x = cvt_tf32(acc[mi][ni][half * 2]     + bias[n64 + dl]);
                        val.y = cvt_tf32(acc[mi][ni][half * 2 + 1] + bias[n64 + dl + 1]);
                        *(float2*)&o[dl] = val;
                    }
                }
            }
        } else {
            float invf[8];
#pragma unroll
            for (int ni = 0; ni < 4; ni++)
#pragma unroll
                for (int c = 0; c < 2; c++)
                    invf[ni * 2 + c] =
                        exp2f(-(float)(ni * 8 + tq * 2 + c) * 0.4152410118609203f);
#pragma unroll
            for (int mi = 0; mi < 2; mi++) {
#pragma unroll
                for (int half = 0; half < 2; half++) {
                    int row = bm + wm * 32 + mi * 16 + g + half * 8;
                    int t = row & (TT - 1), b = row >> 11;
                    float* o = dst + ((size_t)((b * HH + h) * TT + t)) * HD;
                    float tf = (float)t;
#pragma unroll
                    for (int ni = 0; ni < 4; ni++) {
#pragma unroll
                        for (int c = 0; c < 2; c++) {
                            int dl = ni * 8 + tq * 2 + c;
                            float v1 = acc[mi][ni][half * 2 + c]     + bias[n64 + dl];
                            float v2 = acc[mi][ni + 4][half * 2 + c] + bias[n64 + dl + 32];
                            float s, cs;
                            sincosf(tf * invf[ni * 2 + c], &s, &cs);
                            o[dl]      = cvt_tf32(v1 * cs - v2 * s);
                            o[dl + 32] = cvt_tf32(v2 * cs + v1 * s);
                        }
                    }
                }
            }
        }
    } else {
#pragma unroll
        for (int ni = 0; ni < 8; ni++) {
            int col = bn + wn * 64 + ni * 8 + tq * 2;
            float b0 = bias[col], b1 = bias[col + 1];
#pragma unroll
            for (int mi = 0; mi < 2; mi++) {
                int row = bm + wm * 32 + mi * 16 + g;
                float2 lo = make_float2(acc[mi][ni][0] + b0, acc[mi][ni][1] + b1);
                float2 hi = make_float2(acc[mi][ni][2] + b0, acc[mi][ni][3] + b1);
                *(float2*)&C[(size_t)row * Nd + col]       = lo;
                *(float2*)&C[(size_t)(row + 8) * Nd + col] = hi;
            }
        }
    }
}

// ---------------------------------------------------------------------------
// Flash attention with TF32 mma.sync + 2-stage cp.async K/V pipeline.
// Per-(warp, kv-tile) ni_max skips S blocks that are FULLY causally masked
// (bit-identical: those entries contributed exactly 0).
// ---------------------------------------------------------------------------
#define AP 68
#define ATTN_SMEM ((128 * AP + 4 * 64 * AP) * 4)

__global__ __launch_bounds__(256, 2) void flash_attn_mma()
{
    extern __shared__ float sm[];
    float* sQ = sm;                      // [128][AP]
    float* sK = sm + 128 * AP;           // [2][64][AP]
    float* sV = sK + 2 * 64 * AP;        // [2][64][AP]

    int bh = blockIdx.y;
    int qt = (int)gridDim.x - 1 - (int)blockIdx.x;   // heavy tiles first
    int tid = threadIdx.x;
    int warp = tid >> 5, lane = tid & 31;
    int g = lane >> 2, q = lane & 3;

    const float* Qh = g_q + (size_t)bh * TT * HD;
    const float* Kh = g_k + (size_t)bh * TT * HD;
    const float* Vh = g_v + (size_t)bh * TT * HD;

    uint32_t uQ = (uint32_t)__cvta_generic_to_shared(sQ);
    uint32_t uK = (uint32_t)__cvta_generic_to_shared(sK);
    uint32_t uV = (uint32_t)__cvta_generic_to_shared(sV);

    int jm = lane >> 3, lrow = lane & 7;
    int a_row = ((jm & 1) << 3) + lrow, a_col = (jm >> 1) << 2;
    int b_row = ((jm >> 1) << 3) + lrow, b_col = (jm & 1) << 2;

    // Prologue: Q (128 rows x 16 chunks = 2048) + KV stage 0 (1024 each).
#pragma unroll
    for (int it = 0; it < 8; it++) {
        int slot = tid + it * 256;
        int r = slot >> 4, c4 = (slot & 15) << 2;
        CP_ASYNC16(uQ + (r * AP + c4) * 4,
                   &Qh[(size_t)(qt * 128 + r) * HD + c4]);
    }
#pragma unroll
    for (int it = 0; it < 4; it++) {
        int slot = tid + it * 256;
        int r = slot >> 4, c4 = (slot & 15) << 2;
        CP_ASYNC16(uK + (r * AP + c4) * 4, &Kh[(size_t)r * HD + c4]);
        CP_ASYNC16(uV + (r * AP + c4) * 4, &Vh[(size_t)r * HD + c4]);
    }
    CP_COMMIT();

    float m0 = -1e30f, m1 = -1e30f, l0 = 0.f, l1 = 0.f;
    float oacc[8][4];
#pragma unroll
    for (int ni = 0; ni < 8; ni++)
#pragma unroll
        for (int c = 0; c < 4; c++) oacc[ni][c] = 0.f;

    int wrow = qt * 128 + warp * 16;     // warp's first Q row
    int row0 = wrow + g;
    int row1 = row0 + 8;

    int ktmax = 2 * qt + 1;
    for (int kt = 0; kt <= ktmax; kt++) {
        if (kt > 0) __syncthreads();   // readers of the stage we overwrite are done
        if (kt < ktmax) {
            int ns = (kt + 1) & 1;
            int kb2 = (kt + 1) * 64;
            uint32_t base = (uint32_t)(ns * 64 * AP) * 4;
#pragma unroll
            for (int it = 0; it < 4; it++) {
                int slot = tid + it * 256;
                int r = slot >> 4, c4 = (slot & 15) << 2;
                CP_ASYNC16(uK + base + (r * AP + c4) * 4,
                           &Kh[(size_t)(kb2 + r) * HD + c4]);
                CP_ASYNC16(uV + base + (r * AP + c4) * 4,
                           &Vh[(size_t)(kb2 + r) * HD + c4]);
            }
            CP_COMMIT();
            CP_WAIT(1);
        } else {
            CP_WAIT(0);
        }
        __syncthreads();

        int s = kt & 1;
        int kb = kt * 64;
        const float* sKs = sK + s * 64 * AP;
        const float* sVs = sV + s * 64 * AP;

        // ni_max: number of 8-col S blocks with at least one unmasked col.
        bool maskt = (kt >= 2 * qt);
        int ni_max = 8;
        if (maskt) {
            int d = wrow + 15 - kb;
            ni_max = d >= 0 ? min((d >> 3) + 1, 8) : 0;
        }

        // S = Q @ K^T (warp: 16 x 64), skipping fully-masked blocks
        float sf[8][4];
#pragma unroll
        for (int ni = 0; ni < 8; ni++)
#pragma unroll
            for (int c = 0; c < 4; c++) sf[ni][c] = 0.f;

        if (ni_max > 0) {
#pragma unroll
            for (int kc8 = 0; kc8 < 8; kc8++) {
                int kc = kc8 * 8;
                uint32_t afr[4];
                uint32_t aad = (uint32_t)__cvta_generic_to_shared(
                    &sQ[(warp * 16 + a_row) * AP + kc + a_col]);
                LDSM_X4(afr[0], afr[1], afr[2], afr[3], aad);
                uint32_t bfr[8][2];
#pragma unroll
                for (int np = 0; np < 4; np++) {
                    uint32_t bad = (uint32_t)__cvta_generic_to_shared(
                        &sKs[(np * 16 + b_row) * AP + kc + b_col]);
                    LDSM_X4(bfr[2 * np][0], bfr[2 * np][1],
                            bfr[2 * np + 1][0], bfr[2 * np + 1][1], bad);
                }
#pragma unroll
                for (int ni = 0; ni < 8; ni++)
                    if (ni < ni_max)
                        MMA_TF32(sf[ni], afr, bfr[ni]);
            }
        }

        // Online softmax on fragments (ni >= ni_max contribute exactly 0)
        float rmax0 = -1e30f, rmax1 = -1e30f;
#pragma unroll
        for (int ni = 0; ni < 8; ni++) {
            if (ni < ni_max) {
                sf[ni][0] *= 0.125f; sf[ni][1] *= 0.125f;
                sf[ni][2] *= 0.125f; sf[ni][3] *= 0.125f;
                if (maskt) {
                    int c0 = kb + ni * 8 + 2 * q, c1 = c0 + 1;
                    if (c0 > row0) sf[ni][0] = -1e30f;
                    if (c1 > row0) sf[ni][1] = -1e30f;
                    if (c0 > row1) sf[ni][2] = -1e30f;
                    if (c1 > row1) sf[ni][3] = -1e30f;
                }
                rmax0 = fmaxf(rmax0, fmaxf(sf[ni][0], sf[ni][1]));
                rmax1 = fmaxf(rmax1, fmaxf(sf[ni][2], sf[ni][3]));
            }
        }
        rmax0 = fmaxf(rmax0, __shfl_xor_sync(0xffffffffu, rmax0, 1));
        rmax0 = fmaxf(rmax0, __shfl_xor_sync(0xffffffffu, rmax0, 2));
        rmax1 = fmaxf(rmax1, __shfl_xor_sync(0xffffffffu, rmax1, 1));
        rmax1 = fmaxf(rmax1, __shfl_xor_sync(0xffffffffu, rmax1, 2));

        float mn0 = fmaxf(m0, rmax0), mn1 = fmaxf(m1, rmax1);
        float al0 = __expf(m0 - mn0), al1 = __expf(m1 - mn1);
        m0 = mn0; m1 = mn1;

        float rs0 = 0.f, rs1 = 0.f;
#pragma unroll
        for (int ni = 0; ni < 8; ni++) {
            if (ni < ni_max) {
                float p0 = cvt_tf32(__expf(sf[ni][0] - mn0));
                float p1 = cvt_tf32(__expf(sf[ni][1] - mn0));
                float p2 = cvt_tf32(__expf(sf[ni][2] - mn1));
                float p3 = cvt_tf32(__expf(sf[ni][3] - mn1));
                sf[ni][0] = p0; sf[ni][1] = p1; sf[ni][2] = p2; sf[ni][3] = p3;
                rs0 += p0 + p1;
                rs1 += p2 + p3;
            }
        }
        rs0 += __shfl_xor_sync(0xffffffffu, rs0, 1);
        rs0 += __shfl_xor_sync(0xffffffffu, rs0, 2);
        rs1 += __shfl_xor_sync(0xffffffffu, rs1, 1);
        rs1 += __shfl_xor_sync(0xffffffffu, rs1, 2);
        l0 = l0 * al0 + rs0;
        l1 = l1 * al1 + rs1;
#pragma unroll
        for (int ni = 0; ni < 8; ni++) {
            oacc[ni][0] *= al0; oacc[ni][1] *= al0;
            oacc[ni][2] *= al1; oacc[ni][3] *= al1;
        }

        // O += P @ V, skipping P col-blocks kc8 >= ni_max (P there is 0)
#pragma unroll
        for (int kc8 = 0; kc8 < 8; kc8++) {
            if (kc8 < ni_max) {
                uint32_t a[4];
                a[0] = __float_as_uint(sf[kc8][0]);
                a[1] = __float_as_uint(sf[kc8][2]);
                a[2] = __float_as_uint(sf[kc8][1]);
                a[3] = __float_as_uint(sf[kc8][3]);
                int cb = kc8 * 8 + 2 * q;
                const float* v0 = &sVs[cb * AP];
                const float* v1 = &sVs[(cb + 1) * AP];
#pragma unroll
                for (int ni = 0; ni < 8; ni++) {
                    int n = ni * 8 + g;
                    uint32_t b[2];
                    b[0] = __float_as_uint(v0[n]);
                    b[1] = __float_as_uint(v1[n]);
                    MMA_TF32(oacc[ni], a, b);
                }
            }
        }
    }

    // Epilogue: normalize, tf32-round (feeds out-proj GEMM), write [B,T,C]
    float inv0 = 1.0f / l0, inv1 = 1.0f / l1;
    int b_ = bh >> 4, h = bh & 15;
    int trow0 = qt * 128 + warp * 16 + g;
#pragma unroll
    for (int ni = 0; ni < 8; ni++) {
        int col = h * HD + ni * 8 + 2 * q;
        float2 lo = make_float2(cvt_tf32(oacc[ni][0] * inv0),
                                cvt_tf32(oacc[ni][1] * inv0));
        float2 hi = make_float2(cvt_tf32(oacc[ni][2] * inv1),
                                cvt_tf32(oacc[ni][3] * inv1));
        *(float2*)&g_att[((size_t)(b_ * TT + trow0)) * CC + col]     = lo;
        *(float2*)&g_att[((size_t)(b_ * TT + trow0 + 8)) * CC + col] = hi;
    }
}

// ---------------------------------------------------------------------------
extern "C" void kernel_launch(void* const* d_in, const int* in_sizes, int n_in,
                              void* d_out, int out_size)
{
    const float* x     = (const float*)d_in[0];
    const float* W_qkv = (const float*)d_in[1];
    const float* b_qkv = (const float*)d_in[2];
    const float* W_out = (const float*)d_in[3];
    const float* b_out = (const float*)d_in[4];
    float* out = (float*)d_out;

    float *xr, *att, *wqkvT, *woutT;
    cudaGetSymbolAddress((void**)&xr,    g_xr);
    cudaGetSymbolAddress((void**)&att,   g_att);
    cudaGetSymbolAddress((void**)&wqkvT, g_wqkvT);
    cudaGetSymbolAddress((void**)&woutT, g_woutT);

    cudaFuncSetAttribute(tf32_gemm<0>,
                         cudaFuncAttributeMaxDynamicSharedMemorySize, GEMM_SMEM);
    cudaFuncSetAttribute(tf32_gemm<1>,
                         cudaFuncAttributeMaxDynamicSharedMemorySize, GEMM_SMEM);
    cudaFuncSetAttribute(flash_attn_mma,
                         cudaFuncAttributeMaxDynamicSharedMemorySize, ATTN_SMEM);

    // 0) Fused prologue: weight transposes (tf32) + x rounding
    prologue_kernel<<<12288, 256>>>(x, W_qkv, W_out);

    // 1) QKV projection + fused bias/RoPE/head-split epilogue
    tf32_gemm<1><<<dim3(NQKV / GBN, MM / GBM), 256, GEMM_SMEM>>>(
        xr, wqkvT, b_qkv, nullptr, NQKV, CC);

    // 2) Causal flash attention (pipelined K/V, diagonal block skip)
    flash_attn_mma<<<dim3(TT / 128, BB * HH), 256, ATTN_SMEM>>>();

    // 3) Output projection
    tf32_gemm<0><<<dim3(CC / GBN, MM / GBM), 256, GEMM_SMEM>>>(
        att, woutT, b_out, out, CC, CC);
}

// round 16
// speedup vs baseline: 1.5291x; 1.0728x over previous
#include <cuda_runtime.h>
#include <math.h>
#include <stdint.h>

#define BB 4
#define TT 2048
#define CC 1024
#define HH 16
#define HD 64
#define MM (BB*TT)          // 8192 rows
#define NQKV (3*CC)         // 3072

// Scratch (device globals; allocation-free per harness rules)
__device__ float g_xr[(size_t)MM * CC];      // x rounded to tf32
__device__ float g_q[(size_t)MM * CC];       // [B,H,T,hd] tf32
__device__ float g_k[(size_t)MM * CC];       // [B,H,T,hd] tf32
__device__ float g_v[(size_t)MM * CC];       // [B,H,T,hd] tf32
__device__ float g_att[(size_t)MM * CC];     // [B,T,C] tf32
__device__ float g_wqkvT[(size_t)NQKV * CC]; // W_qkv^T [3072][1024], tf32
__device__ float g_woutT[(size_t)CC * CC];   // W_out^T [1024][1024], tf32

// ---------------------------------------------------------------------------
// Helpers
// ---------------------------------------------------------------------------
__device__ __forceinline__ float cvt_tf32(float x) {
    uint32_t r;
    asm("cvt.rna.tf32.f32 %0, %1;" : "=r"(r) : "f"(x));
    return __uint_as_float(r);
}

#define LDSM_X4(r0, r1, r2, r3, addr)                                         \
    asm volatile("ldmatrix.sync.aligned.m8n8.x4.shared.b16 {%0,%1,%2,%3}, [%4];" \
                 : "=r"(r0), "=r"(r1), "=r"(r2), "=r"(r3) : "r"(addr))

#define MMA_TF32(d, a, b)                                                     \
    asm volatile("mma.sync.aligned.m16n8k8.row.col.f32.tf32.tf32.f32 "        \
                 "{%0,%1,%2,%3}, {%4,%5,%6,%7}, {%8,%9}, {%0,%1,%2,%3};"      \
                 : "+f"(d[0]), "+f"(d[1]), "+f"(d[2]), "+f"(d[3])             \
                 : "r"(a[0]), "r"(a[1]), "r"(a[2]), "r"(a[3]),                \
                   "r"(b[0]), "r"(b[1]))

#define CP_ASYNC16(dst, src)                                                  \
    asm volatile("cp.async.cg.shared.global [%0], [%1], 16;"                  \
                 :: "r"(dst), "l"(src))
#define CP_COMMIT() asm volatile("cp.async.commit_group;")
#define CP_WAIT(n)  asm volatile("cp.async.wait_group %0;" :: "n"(n))

// ---------------------------------------------------------------------------
// Fused prologue: transpose W_qkv + transpose W_out (tf32) + round x (tf32).
// ---------------------------------------------------------------------------
__global__ __launch_bounds__(256) void prologue_kernel(
    const float* __restrict__ x,
    const float* __restrict__ W_qkv,
    const float* __restrict__ W_out)
{
    int bid = blockIdx.x;
    if (bid < 4096) {
        __shared__ float tile[32][33];
        const float* W;
        float* Wt;
        int n0, k0, K, N;
        if (bid < 3072) {
            W = W_qkv; Wt = g_wqkvT; K = CC; N = NQKV;
            n0 = (bid % 96) * 32; k0 = (bid / 96) * 32;
        } else {
            int id = bid - 3072;
            W = W_out; Wt = g_woutT; K = CC; N = CC;
            n0 = (id & 31) * 32; k0 = (id >> 5) * 32;
        }
        int tx = threadIdx.x & 31, ty = threadIdx.x >> 5;
#pragma unroll
        for (int i = 0; i < 32; i += 8)
            tile[ty + i][tx] = W[(size_t)(k0 + ty + i) * N + n0 + tx];
        __syncthreads();
#pragma unroll
        for (int i = 0; i < 32; i += 8)
            Wt[(size_t)(n0 + ty + i) * K + k0 + tx] = cvt_tf32(tile[tx][ty + i]);
    } else {
        size_t i = ((size_t)(bid - 4096) * 256 + threadIdx.x) * 4;
        float4 v = *(const float4*)&x[i];
        v.x = cvt_tf32(v.x); v.y = cvt_tf32(v.y);
        v.z = cvt_tf32(v.z); v.w = cvt_tf32(v.w);
        *(float4*)&g_xr[i] = v;
    }
}

// ---------------------------------------------------------------------------
// TF32 tensor-core GEMM, 2-stage cp.async double buffer (R10-exact).
// ---------------------------------------------------------------------------
#define GBM 128
#define GBN 128
#define GBK 32
#define GPAD 36
#define GEMM_SMEM (2 * (GBM + GBN) * GPAD * 4)

template <int ROPE>
__global__ __launch_bounds__(256, 2) void tf32_gemm(
    const float* __restrict__ A, const float* __restrict__ Bt,
    const float* __restrict__ bias, float* __restrict__ C,
    int Nd, int Kd)
{
    extern __shared__ float smem[];
    float* Asm = smem;                       // [2][GBM*GPAD]
    float* Bsm = smem + 2 * GBM * GPAD;      // [2][GBN*GPAD]

    int tid  = threadIdx.x;
    int warp = tid >> 5, lane = tid & 31;
    int wm   = warp >> 1;
    int wn   = warp & 1;
    int bm   = blockIdx.y * GBM, bn = blockIdx.x * GBN;

    float acc[2][8][4];
#pragma unroll
    for (int mi = 0; mi < 2; mi++)
#pragma unroll
        for (int ni = 0; ni < 8; ni++)
#pragma unroll
            for (int c = 0; c < 4; c++) acc[mi][ni][c] = 0.f;

    int j = lane >> 3;
    int lrow = lane & 7;
    int a_row = ((j & 1) << 3) + lrow;
    int a_col = (j >> 1) << 2;
    int b_row = ((j >> 1) << 3) + lrow;
    int b_col = (j & 1) << 2;

    int cr = tid >> 3;             // 0..31 base row
    int ccq = (tid & 7) << 2;      // col (float4)

    uint32_t sA[2], sB[2];
#pragma unroll
    for (int bf = 0; bf < 2; bf++) {
        sA[bf] = (uint32_t)__cvta_generic_to_shared(&Asm[bf * GBM * GPAD]);
        sB[bf] = (uint32_t)__cvta_generic_to_shared(&Bsm[bf * GBN * GPAD]);
    }

#define GEMM_ISSUE(buf, k0)                                                   \
    {                                                                         \
        _Pragma("unroll")                                                     \
        for (int it = 0; it < 4; it++) {                                      \
            int r = cr + it * 32;                                             \
            uint32_t da = sA[buf] + (r * GPAD + ccq) * 4;                     \
            const float* pa = &A[(size_t)(bm + r) * Kd + (k0) + ccq];         \
            CP_ASYNC16(da, pa);                                               \
            uint32_t db = sB[buf] + (r * GPAD + ccq) * 4;                     \
            const float* pb = &Bt[(size_t)(bn + r) * Kd + (k0) + ccq];        \
            CP_ASYNC16(db, pb);                                               \
        }                                                                     \
        CP_COMMIT();                                                          \
    }

    int iters = Kd / GBK;
    GEMM_ISSUE(0, 0);

    for (int i = 0; i < iters; i++) {
        if (i + 1 < iters) {
            GEMM_ISSUE((i + 1) & 1, (i + 1) * GBK);
            CP_WAIT(1);
        } else {
            CP_WAIT(0);
        }
        __syncthreads();

        const float* As = &Asm[(i & 1) * GBM * GPAD];
        const float* Bs = &Bsm[(i & 1) * GBN * GPAD];

#pragma unroll
        for (int ks = 0; ks < 4; ks++) {
            int kc = ks * 8;
            uint32_t afr[2][4];
#pragma unroll
            for (int mi = 0; mi < 2; mi++) {
                int mr = wm * 32 + mi * 16;
                uint32_t addr = (uint32_t)__cvta_generic_to_shared(
                    &As[(mr + a_row) * GPAD + kc + a_col]);
                LDSM_X4(afr[mi][0], afr[mi][1], afr[mi][2], afr[mi][3], addr);
            }
            uint32_t bfr[8][2];
#pragma unroll
            for (int np = 0; np < 4; np++) {
                int nb = wn * 64 + np * 16;
                uint32_t addr = (uint32_t)__cvta_generic_to_shared(
                    &Bs[(nb + b_row) * GPAD + kc + b_col]);
                LDSM_X4(bfr[2 * np][0], bfr[2 * np][1],
                        bfr[2 * np + 1][0], bfr[2 * np + 1][1], addr);
            }
#pragma unroll
            for (int mi = 0; mi < 2; mi++)
#pragma unroll
                for (int ni = 0; ni < 8; ni++)
                    MMA_TF32(acc[mi][ni], afr[mi], bfr[ni]);
        }
        __syncthreads();
    }

    int g = lane >> 2, tq = lane & 3;

    if (ROPE) {
        int n64 = bn + wn * 64;
        int sel = n64 >> 10;             // 0=q, 1=k, 2=v
        int h   = (n64 >> 6) & (HH - 1);
        float* dst = (sel == 0) ? g_q : (sel == 1) ? g_k : g_v;

        if (sel == 2) {
#pragma unroll
            for (int mi = 0; mi < 2; mi++) {
#pragma unroll
                for (int half = 0; half < 2; half++) {
                    int row = bm + wm * 32 + mi * 16 + g + half * 8;
                    int t = row & (TT - 1), b = row >> 11;
                    float* o = dst + ((size_t)((b * HH + h) * TT + t)) * HD;
#pragma unroll
                    for (int ni = 0; ni < 8; ni++) {
                        int dl = ni * 8 + tq * 2;
                        float2 val;
                        val.x = cvt_tf32(acc[mi][ni][half * 2]     + bias[n64 + dl]);
                        val.y = cvt_tf32(acc[mi][ni][half * 2 + 1] + bias[n64 + dl + 1]);
                        *(float2*)&o[dl] = val;
                    }
                }
            }
        } else {
            float invf[8];
#pragma unroll
            for (int ni = 0; ni < 4; ni++)
#pragma unroll
                for (int c = 0; c < 2; c++)
                    invf[ni * 2 + c] =
                        exp2f(-(float)(ni * 8 + tq * 2 + c) * 0.4152410118609203f);
#pragma unroll
            for (int mi = 0; mi < 2; mi++) {
#pragma unroll
                for (int half = 0; half < 2; half++) {
                    int row = bm + wm * 32 + mi * 16 + g + half * 8;
                    int t = row & (TT - 1), b = row >> 11;
                    float* o = dst + ((size_t)((b * HH + h) * TT + t)) * HD;
                    float tf = (float)t;
#pragma unroll
                    for (int ni = 0; ni < 4; ni++) {
#pragma unroll
                        for (int c = 0; c < 2; c++) {
                            int dl = ni * 8 + tq * 2 + c;
                            float v1 = acc[mi][ni][half * 2 + c]     + bias[n64 + dl];
                            float v2 = acc[mi][ni + 4][half * 2 + c] + bias[n64 + dl + 32];
                            float s, cs;
                            sincosf(tf * invf[ni * 2 + c], &s, &cs);
                            o[dl]      = cvt_tf32(v1 * cs - v2 * s);
                            o[dl + 32] = cvt_tf32(v2 * cs + v1 * s);
                        }
                    }
                }
            }
        }
    } else {
#pragma unroll
        for (int ni = 0; ni < 8; ni++) {
            int col = bn + wn * 64 + ni * 8 + tq * 2;
            float b0 = bias[col], b1 = bias[col + 1];
#pragma unroll
            for (int mi = 0; mi < 2; mi++) {
                int row = bm + wm * 32 + mi * 16 + g;
                float2 lo = make_float2(acc[mi][ni][0] + b0, acc[mi][ni][1] + b1);
                float2 hi = make_float2(acc[mi][ni][2] + b0, acc[mi][ni][3] + b1);
                *(float2*)&C[(size_t)row * Nd + col]       = lo;
                *(float2*)&C[(size_t)(row + 8) * Nd + col] = hi;
            }
        }
    }
}

// ---------------------------------------------------------------------------
// Flash attention, TF32 mma.sync + 2-stage cp.async K/V pipeline.
// R16: warp-uniform 3-way tile classification:
//   FULL (tile below diagonal)  -> branch-free R10-exact body
//   DIAG (straddles diagonal)   -> masked body with ni_max block skip
//   SKIP (above diagonal)       -> no compute (bit-identical: contributes 0)
// ---------------------------------------------------------------------------
#define AP 68
#define ATTN_SMEM ((128 * AP + 4 * 64 * AP) * 4)

__global__ __launch_bounds__(256, 2) void flash_attn_mma()
{
    extern __shared__ float sm[];
    float* sQ = sm;                      // [128][AP]
    float* sK = sm + 128 * AP;           // [2][64][AP]
    float* sV = sK + 2 * 64 * AP;        // [2][64][AP]

    int bh = blockIdx.y;
    int qt = (int)gridDim.x - 1 - (int)blockIdx.x;   // heavy tiles first
    int tid = threadIdx.x;
    int warp = tid >> 5, lane = tid & 31;
    int g = lane >> 2, q = lane & 3;

    const float* Qh = g_q + (size_t)bh * TT * HD;
    const float* Kh = g_k + (size_t)bh * TT * HD;
    const float* Vh = g_v + (size_t)bh * TT * HD;

    uint32_t uQ = (uint32_t)__cvta_generic_to_shared(sQ);
    uint32_t uK = (uint32_t)__cvta_generic_to_shared(sK);
    uint32_t uV = (uint32_t)__cvta_generic_to_shared(sV);

    int jm = lane >> 3, lrow = lane & 7;
    int a_row = ((jm & 1) << 3) + lrow, a_col = (jm >> 1) << 2;
    int b_row = ((jm >> 1) << 3) + lrow, b_col = (jm & 1) << 2;

    // Prologue: Q (2048 chunks) + KV stage 0 (1024 each).
#pragma unroll
    for (int it = 0; it < 8; it++) {
        int slot = tid + it * 256;
        int r = slot >> 4, c4 = (slot & 15) << 2;
        CP_ASYNC16(uQ + (r * AP + c4) * 4,
                   &Qh[(size_t)(qt * 128 + r) * HD + c4]);
    }
#pragma unroll
    for (int it = 0; it < 4; it++) {
        int slot = tid + it * 256;
        int r = slot >> 4, c4 = (slot & 15) << 2;
        CP_ASYNC16(uK + (r * AP + c4) * 4, &Kh[(size_t)r * HD + c4]);
        CP_ASYNC16(uV + (r * AP + c4) * 4, &Vh[(size_t)r * HD + c4]);
    }
    CP_COMMIT();

    float m0 = -1e30f, m1 = -1e30f, l0 = 0.f, l1 = 0.f;
    float oacc[8][4];
#pragma unroll
    for (int ni = 0; ni < 8; ni++)
#pragma unroll
        for (int c = 0; c < 4; c++) oacc[ni][c] = 0.f;

    int wrow = qt * 128 + warp * 16;     // warp's first Q row
    int row0 = wrow + g;
    int row1 = row0 + 8;

    int ktmax = 2 * qt + 1;
    for (int kt = 0; kt <= ktmax; kt++) {
        if (kt > 0) __syncthreads();
        if (kt < ktmax) {
            int ns = (kt + 1) & 1;
            int kb2 = (kt + 1) * 64;
            uint32_t base = (uint32_t)(ns * 64 * AP) * 4;
#pragma unroll
            for (int it = 0; it < 4; it++) {
                int slot = tid + it * 256;
                int r = slot >> 4, c4 = (slot & 15) << 2;
                CP_ASYNC16(uK + base + (r * AP + c4) * 4,
                           &Kh[(size_t)(kb2 + r) * HD + c4]);
                CP_ASYNC16(uV + base + (r * AP + c4) * 4,
                           &Vh[(size_t)(kb2 + r) * HD + c4]);
            }
            CP_COMMIT();
            CP_WAIT(1);
        } else {
            CP_WAIT(0);
        }
        __syncthreads();

        int s = kt & 1;
        int kb = kt * 64;
        const float* sKs = sK + s * 64 * AP;
        const float* sVs = sV + s * 64 * AP;

        if (kb + 63 <= wrow) {
            // ---------------- FULL path (R10-exact, branch-free) ----------
            float sf[8][4];
#pragma unroll
            for (int ni = 0; ni < 8; ni++)
#pragma unroll
                for (int c = 0; c < 4; c++) sf[ni][c] = 0.f;

#pragma unroll
            for (int kc8 = 0; kc8 < 8; kc8++) {
                int kc = kc8 * 8;
                uint32_t afr[4];
                uint32_t aad = (uint32_t)__cvta_generic_to_shared(
                    &sQ[(warp * 16 + a_row) * AP + kc + a_col]);
                LDSM_X4(afr[0], afr[1], afr[2], afr[3], aad);
                uint32_t bfr[8][2];
#pragma unroll
                for (int np = 0; np < 4; np++) {
                    uint32_t bad = (uint32_t)__cvta_generic_to_shared(
                        &sKs[(np * 16 + b_row) * AP + kc + b_col]);
                    LDSM_X4(bfr[2 * np][0], bfr[2 * np][1],
                            bfr[2 * np + 1][0], bfr[2 * np + 1][1], bad);
                }
#pragma unroll
                for (int ni = 0; ni < 8; ni++)
                    MMA_TF32(sf[ni], afr, bfr[ni]);
            }

            float rmax0 = -1e30f, rmax1 = -1e30f;
#pragma unroll
            for (int ni = 0; ni < 8; ni++) {
                sf[ni][0] *= 0.125f; sf[ni][1] *= 0.125f;
                sf[ni][2] *= 0.125f; sf[ni][3] *= 0.125f;
                rmax0 = fmaxf(rmax0, fmaxf(sf[ni][0], sf[ni][1]));
                rmax1 = fmaxf(rmax1, fmaxf(sf[ni][2], sf[ni][3]));
            }
            rmax0 = fmaxf(rmax0, __shfl_xor_sync(0xffffffffu, rmax0, 1));
            rmax0 = fmaxf(rmax0, __shfl_xor_sync(0xffffffffu, rmax0, 2));
            rmax1 = fmaxf(rmax1, __shfl_xor_sync(0xffffffffu, rmax1, 1));
            rmax1 = fmaxf(rmax1, __shfl_xor_sync(0xffffffffu, rmax1, 2));

            float mn0 = fmaxf(m0, rmax0), mn1 = fmaxf(m1, rmax1);
            float al0 = __expf(m0 - mn0), al1 = __expf(m1 - mn1);
            m0 = mn0; m1 = mn1;

            float rs0 = 0.f, rs1 = 0.f;
#pragma unroll
            for (int ni = 0; ni < 8; ni++) {
                float p0 = cvt_tf32(__expf(sf[ni][0] - mn0));
                float p1 = cvt_tf32(__expf(sf[ni][1] - mn0));
                float p2 = cvt_tf32(__expf(sf[ni][2] - mn1));
                float p3 = cvt_tf32(__expf(sf[ni][3] - mn1));
                sf[ni][0] = p0; sf[ni][1] = p1; sf[ni][2] = p2; sf[ni][3] = p3;
                rs0 += p0 + p1;
                rs1 += p2 + p3;
            }
            rs0 += __shfl_xor_sync(0xffffffffu, rs0, 1);
            rs0 += __shfl_xor_sync(0xffffffffu, rs0, 2);
            rs1 += __shfl_xor_sync(0xffffffffu, rs1, 1);
            rs1 += __shfl_xor_sync(0xffffffffu, rs1, 2);
            l0 = l0 * al0 + rs0;
            l1 = l1 * al1 + rs1;
#pragma unroll
            for (int ni = 0; ni < 8; ni++) {
                oacc[ni][0] *= al0; oacc[ni][1] *= al0;
                oacc[ni][2] *= al1; oacc[ni][3] *= al1;
            }

#pragma unroll
            for (int kc8 = 0; kc8 < 8; kc8++) {
                uint32_t a[4];
                a[0] = __float_as_uint(sf[kc8][0]);
                a[1] = __float_as_uint(sf[kc8][2]);
                a[2] = __float_as_uint(sf[kc8][1]);
                a[3] = __float_as_uint(sf[kc8][3]);
                int cb = kc8 * 8 + 2 * q;
                const float* v0 = &sVs[cb * AP];
                const float* v1 = &sVs[(cb + 1) * AP];
#pragma unroll
                for (int ni = 0; ni < 8; ni++) {
                    int n = ni * 8 + g;
                    uint32_t b[2];
                    b[0] = __float_as_uint(v0[n]);
                    b[1] = __float_as_uint(v1[n]);
                    MMA_TF32(oacc[ni], a, b);
                }
            }
        } else if (kb <= wrow + 15) {
            // ---------------- DIAGONAL path (masked, block-skip) ----------
            int d = wrow + 15 - kb;
            int ni_max = min((d >> 3) + 1, 8);

            float sf[8][4];
#pragma unroll
            for (int ni = 0; ni < 8; ni++)
#pragma unroll
                for (int c = 0; c < 4; c++) sf[ni][c] = 0.f;

#pragma unroll
            for (int kc8 = 0; kc8 < 8; kc8++) {
                int kc = kc8 * 8;
                uint32_t afr[4];
                uint32_t aad = (uint32_t)__cvta_generic_to_shared(
                    &sQ[(warp * 16 + a_row) * AP + kc + a_col]);
                LDSM_X4(afr[0], afr[1], afr[2], afr[3], aad);
                uint32_t bfr[8][2];
#pragma unroll
                for (int np = 0; np < 4; np++) {
                    uint32_t bad = (uint32_t)__cvta_generic_to_shared(
                        &sKs[(np * 16 + b_row) * AP + kc + b_col]);
                    LDSM_X4(bfr[2 * np][0], bfr[2 * np][1],
                            bfr[2 * np + 1][0], bfr[2 * np + 1][1], bad);
                }
#pragma unroll
                for (int ni = 0; ni < 8; ni++)
                    if (ni < ni_max)
                        MMA_TF32(sf[ni], afr, bfr[ni]);
            }

            float rmax0 = -1e30f, rmax1 = -1e30f;
#pragma unroll
            for (int ni = 0; ni < 8; ni++) {
                if (ni < ni_max) {
                    sf[ni][0] *= 0.125f; sf[ni][1] *= 0.125f;
                    sf[ni][2] *= 0.125f; sf[ni][3] *= 0.125f;
                    int c0 = kb + ni * 8 + 2 * q, c1 = c0 + 1;
                    if (c0 > row0) sf[ni][0] = -1e30f;
                    if (c1 > row0) sf[ni][1] = -1e30f;
                    if (c0 > row1) sf[ni][2] = -1e30f;
                    if (c1 > row1) sf[ni][3] = -1e30f;
                    rmax0 = fmaxf(rmax0, fmaxf(sf[ni][0], sf[ni][1]));
                    rmax1 = fmaxf(rmax1, fmaxf(sf[ni][2], sf[ni][3]));
                }
            }
            rmax0 = fmaxf(rmax0, __shfl_xor_sync(0xffffffffu, rmax0, 1));
            rmax0 = fmaxf(rmax0, __shfl_xor_sync(0xffffffffu, rmax0, 2));
            rmax1 = fmaxf(rmax1, __shfl_xor_sync(0xffffffffu, rmax1, 1));
            rmax1 = fmaxf(rmax1, __shfl_xor_sync(0xffffffffu, rmax1, 2));

            float mn0 = fmaxf(m0, rmax0), mn1 = fmaxf(m1, rmax1);
            float al0 = __expf(m0 - mn0), al1 = __expf(m1 - mn1);
            m0 = mn0; m1 = mn1;

            float rs0 = 0.f, rs1 = 0.f;
#pragma unroll
            for (int ni = 0; ni < 8; ni++) {
                if (ni < ni_max) {
                    float p0 = cvt_tf32(__expf(sf[ni][0] - mn0));
                    float p1 = cvt_tf32(__expf(sf[ni][1] - mn0));
                    float p2 = cvt_tf32(__expf(sf[ni][2] - mn1));
                    float p3 = cvt_tf32(__expf(sf[ni][3] - mn1));
                    sf[ni][0] = p0; sf[ni][1] = p1; sf[ni][2] = p2; sf[ni][3] = p3;
                    rs0 += p0 + p1;
                    rs1 += p2 + p3;
                }
            }
            rs0 += __shfl_xor_sync(0xffffffffu, rs0, 1);
            rs0 += __shfl_xor_sync(0xffffffffu, rs0, 2);
            rs1 += __shfl_xor_sync(0xffffffffu, rs1, 1);
            rs1 += __shfl_xor_sync(0xffffffffu, rs1, 2);
            l0 = l0 * al0 + rs0;
            l1 = l1 * al1 + rs1;
#pragma unroll
            for (int ni = 0; ni < 8; ni++) {
                oacc[ni][0] *= al0; oacc[ni][1] *= al0;
                oacc[ni][2] *= al1; oacc[ni][3] *= al1;
            }

#pragma unroll
            for (int kc8 = 0; kc8 < 8; kc8++) {
                if (kc8 < ni_max) {
                    uint32_t a[4];
                    a[0] = __float_as_uint(sf[kc8][0]);
                    a[1] = __float_as_uint(sf[kc8][2]);
                    a[2] = __float_as_uint(sf[kc8][1]);
                    a[3] = __float_as_uint(sf[kc8][3]);
                    int cb = kc8 * 8 + 2 * q;
                    const float* v0 = &sVs[cb * AP];
                    const float* v1 = &sVs[(cb + 1) * AP];
#pragma unroll
                    for (int ni = 0; ni < 8; ni++) {
                        int n = ni * 8 + g;
                        uint32_t b[2];
                        b[0] = __float_as_uint(v0[n]);
                        b[1] = __float_as_uint(v1[n]);
                        MMA_TF32(oacc[ni], a, b);
                    }
                }
            }
        }
        // else: tile fully above diagonal for this warp — contributes exactly
        // 0 (alpha=1, rs=0); skip all compute. Barriers above are unconditional.
    }

    // Epilogue: normalize, tf32-round (feeds out-proj GEMM), write [B,T,C]
    float inv0 = 1.0f / l0, inv1 = 1.0f / l1;
    int b_ = bh >> 4, h = bh & 15;
    int trow0 = qt * 128 + warp * 16 + g;
#pragma unroll
    for (int ni = 0; ni < 8; ni++) {
        int col = h * HD + ni * 8 + 2 * q;
        float2 lo = make_float2(cvt_tf32(oacc[ni][0] * inv0),
                                cvt_tf32(oacc[ni][1] * inv0));
        float2 hi = make_float2(cvt_tf32(oacc[ni][2] * inv1),
                                cvt_tf32(oacc[ni][3] * inv1));
        *(float2*)&g_att[((size_t)(b_ * TT + trow0)) * CC + col]     = lo;
        *(float2*)&g_att[((size_t)(b_ * TT + trow0 + 8)) * CC + col] = hi;
    }
}

// ---------------------------------------------------------------------------
extern "C" void kernel_launch(void* const* d_in, const int* in_sizes, int n_in,
                              void* d_out, int out_size)
{
    const float* x     = (const float*)d_in[0];
    const float* W_qkv = (const float*)d_in[1];
    const float* b_qkv = (const float*)d_in[2];
    const float* W_out = (const float*)d_in[3];
    const float* b_out = (const float*)d_in[4];
    float* out = (float*)d_out;

    float *xr, *att, *wqkvT, *woutT;
    cudaGetSymbolAddress((void**)&xr,    g_xr);
    cudaGetSymbolAddress((void**)&att,   g_att);
    cudaGetSymbolAddress((void**)&wqkvT, g_wqkvT);
    cudaGetSymbolAddress((void**)&woutT, g_woutT);

    cudaFuncSetAttribute(tf32_gemm<0>,
                         cudaFuncAttributeMaxDynamicSharedMemorySize, GEMM_SMEM);
    cudaFuncSetAttribute(tf32_gemm<1>,
                         cudaFuncAttributeMaxDynamicSharedMemorySize, GEMM_SMEM);
    cudaFuncSetAttribute(flash_attn_mma,
                         cudaFuncAttributeMaxDynamicSharedMemorySize, ATTN_SMEM);

    // 0) Fused prologue: weight transposes (tf32) + x rounding
    prologue_kernel<<<12288, 256>>>(x, W_qkv, W_out);

    // 1) QKV projection + fused bias/RoPE/head-split epilogue
    tf32_gemm<1><<<dim3(NQKV / GBN, MM / GBM), 256, GEMM_SMEM>>>(
        xr, wqkvT, b_qkv, nullptr, NQKV, CC);

    // 2) Causal flash attention (pipelined K/V, 3-way tile classification)
    flash_attn_mma<<<dim3(TT / 128, BB * HH), 256, ATTN_SMEM>>>();

    // 3) Output projection
    tf32_gemm<0><<<dim3(CC / GBN, MM / GBM), 256, GEMM_SMEM>>>(
        att, woutT, b_out, out, CC, CC);
}

// round 17
// speedup vs baseline: 2.1184x; 1.3854x over previous
#include <cuda_runtime.h>
#include <cuda_fp16.h>
#include <math.h>
#include <stdint.h>

#define BB 4
#define TT 2048
#define CC 1024
#define HH 16
#define HD 64
#define MM (BB*TT)          // 8192 rows
#define NQKV (3*CC)         // 3072

// Scratch (device globals; allocation-free per harness rules)
__device__ __half g_xh[(size_t)MM * CC];      // x rounded to fp16
__device__ float  g_q[(size_t)MM * CC];       // [B,H,T,hd] tf32 (attention)
__device__ float  g_k[(size_t)MM * CC];       // [B,H,T,hd] tf32
__device__ float  g_v[(size_t)MM * CC];       // [B,H,T,hd] tf32
__device__ __half g_att[(size_t)MM * CC];     // [B,T,C] fp16
__device__ __half g_wqkvT[(size_t)NQKV * CC]; // W_qkv^T [3072][1024] fp16
__device__ __half g_woutT[(size_t)CC * CC];   // W_out^T [1024][1024] fp16

// ---------------------------------------------------------------------------
// Helpers
// ---------------------------------------------------------------------------
__device__ __forceinline__ float cvt_tf32(float x) {
    uint32_t r;
    asm("cvt.rna.tf32.f32 %0, %1;" : "=r"(r) : "f"(x));
    return __uint_as_float(r);
}

#define LDSM_X4(r0, r1, r2, r3, addr)                                         \
    asm volatile("ldmatrix.sync.aligned.m8n8.x4.shared.b16 {%0,%1,%2,%3}, [%4];" \
                 : "=r"(r0), "=r"(r1), "=r"(r2), "=r"(r3) : "r"(addr))

#define MMA_TF32(d, a, b)                                                     \
    asm volatile("mma.sync.aligned.m16n8k8.row.col.f32.tf32.tf32.f32 "        \
                 "{%0,%1,%2,%3}, {%4,%5,%6,%7}, {%8,%9}, {%0,%1,%2,%3};"      \
                 : "+f"(d[0]), "+f"(d[1]), "+f"(d[2]), "+f"(d[3])             \
                 : "r"(a[0]), "r"(a[1]), "r"(a[2]), "r"(a[3]),                \
                   "r"(b[0]), "r"(b[1]))

#define MMA_F16(d, a, b)                                                      \
    asm volatile("mma.sync.aligned.m16n8k16.row.col.f32.f16.f16.f32 "         \
                 "{%0,%1,%2,%3}, {%4,%5,%6,%7}, {%8,%9}, {%0,%1,%2,%3};"      \
                 : "+f"(d[0]), "+f"(d[1]), "+f"(d[2]), "+f"(d[3])             \
                 : "r"(a[0]), "r"(a[1]), "r"(a[2]), "r"(a[3]),                \
                   "r"(b[0]), "r"(b[1]))

#define CP_ASYNC16(dst, src)                                                  \
    asm volatile("cp.async.cg.shared.global [%0], [%1], 16;"                  \
                 :: "r"(dst), "l"(src))
#define CP_COMMIT() asm volatile("cp.async.commit_group;")
#define CP_WAIT(n)  asm volatile("cp.async.wait_group %0;" :: "n"(n))

// ---------------------------------------------------------------------------
// Fused prologue: transpose W_qkv + W_out (fp16) + round x (fp16).
// ---------------------------------------------------------------------------
__global__ __launch_bounds__(256) void prologue_kernel(
    const float* __restrict__ x,
    const float* __restrict__ W_qkv,
    const float* __restrict__ W_out)
{
    int bid = blockIdx.x;
    if (bid < 4096) {
        __shared__ float tile[32][33];
        const float* W;
        __half* Wt;
        int n0, k0, K, N;
        if (bid < 3072) {
            W = W_qkv; Wt = g_wqkvT; K = CC; N = NQKV;
            n0 = (bid % 96) * 32; k0 = (bid / 96) * 32;
        } else {
            int id = bid - 3072;
            W = W_out; Wt = g_woutT; K = CC; N = CC;
            n0 = (id & 31) * 32; k0 = (id >> 5) * 32;
        }
        int tx = threadIdx.x & 31, ty = threadIdx.x >> 5;
#pragma unroll
        for (int i = 0; i < 32; i += 8)
            tile[ty + i][tx] = W[(size_t)(k0 + ty + i) * N + n0 + tx];
        __syncthreads();
#pragma unroll
        for (int i = 0; i < 32; i += 8)
            Wt[(size_t)(n0 + ty + i) * K + k0 + tx] =
                __float2half_rn(tile[tx][ty + i]);
    } else {
        size_t i = ((size_t)(bid - 4096) * 256 + threadIdx.x) * 4;
        float4 v = *(const float4*)&x[i];
        half2* o = (half2*)&g_xh[i];
        o[0] = __floats2half2_rn(v.x, v.y);
        o[1] = __floats2half2_rn(v.z, v.w);
    }
}

// ---------------------------------------------------------------------------
// FP16 tensor-core GEMM (m16n8k16, fp32 accum), 2-stage cp.async ring.
// Tile 128x128, K-chunk 64 halves (4 ks steps x 16 MMAs = 64 MMAs/barrier).
// Row stride 72 halves (144B): conflict-free ldmatrix, 16B-aligned cp.async.
// ROPE=0: C = A @ Bt^T + bias (fp32 out).  ROPE=1: epilogue = bias + RoPE +
// head split -> fp32 tf32-rounded g_q/g_k/g_v.
// ---------------------------------------------------------------------------
#define GBM 128
#define GBN 128
#define HBK 64
#define HSTR 72
#define TILEH (GBM * HSTR)                    // halves per tile
#define GEMM_SMEM (4 * TILEH * 2)             // 2 ops x 2 stages, bytes

template <int ROPE>
__global__ __launch_bounds__(256, 2) void f16_gemm(
    const __half* __restrict__ A, const __half* __restrict__ Bt,
    const float* __restrict__ bias, float* __restrict__ C,
    int Nd, int Kd)
{
    extern __shared__ __half hsm[];
    // Layout: [A0][A1][B0][B1], each TILEH halves.
    int tid  = threadIdx.x;
    int warp = tid >> 5, lane = tid & 31;
    int wm   = warp >> 1;
    int wn   = warp & 1;
    int bm   = blockIdx.y * GBM, bn = blockIdx.x * GBN;

    float acc[2][8][4];
#pragma unroll
    for (int mi = 0; mi < 2; mi++)
#pragma unroll
        for (int ni = 0; ni < 8; ni++)
#pragma unroll
            for (int c = 0; c < 4; c++) acc[mi][ni][c] = 0.f;

    // A frag (m16k16): row = lane&15, col8 = (lane>>4)*8
    int a_row = lane & 15;
    int a_c8  = (lane >> 4) << 3;
    // B frag (2 n-blocks per x4): rows nb+((lane>>4)*8 + (lane&7)), col8 = ((lane>>3)&1)*8
    int b_row = ((lane >> 4) << 3) + (lane & 7);
    int b_c8  = ((lane >> 3) & 1) << 3;

    uint32_t sA[2], sB[2];
#pragma unroll
    for (int bf = 0; bf < 2; bf++) {
        sA[bf] = (uint32_t)__cvta_generic_to_shared(&hsm[bf * TILEH]);
        sB[bf] = (uint32_t)__cvta_generic_to_shared(&hsm[(2 + bf) * TILEH]);
    }

    // Stage: 128 rows x 8 chunks (8 halves) = 1024 slots per operand, 4/thread.
#define H_ISSUE(buf, k0)                                                      \
    {                                                                         \
        _Pragma("unroll")                                                     \
        for (int it = 0; it < 4; it++) {                                      \
            int slot = tid + it * 256;                                        \
            int r = slot >> 3, c8 = (slot & 7) << 3;                          \
            CP_ASYNC16(sA[buf] + (r * HSTR + c8) * 2,                         \
                       &A[(size_t)(bm + r) * Kd + (k0) + c8]);                \
            CP_ASYNC16(sB[buf] + (r * HSTR + c8) * 2,                         \
                       &Bt[(size_t)(bn + r) * Kd + (k0) + c8]);               \
        }                                                                     \
        CP_COMMIT();                                                          \
    }

    int iters = Kd / HBK;
    H_ISSUE(0, 0);

    for (int i = 0; i < iters; i++) {
        if (i + 1 < iters) {
            H_ISSUE((i + 1) & 1, (i + 1) * HBK);
            CP_WAIT(1);
        } else {
            CP_WAIT(0);
        }
        __syncthreads();

        const __half* As = &hsm[(i & 1) * TILEH];
        const __half* Bs = &hsm[(2 + (i & 1)) * TILEH];

#pragma unroll
        for (int ks = 0; ks < 4; ks++) {
            int kc = ks * 16;
            uint32_t afr[2][4];
#pragma unroll
            for (int mi = 0; mi < 2; mi++) {
                int mr = wm * 32 + mi * 16;
                uint32_t addr = (uint32_t)__cvta_generic_to_shared(
                    &As[(mr + a_row) * HSTR + kc + a_c8]);
                LDSM_X4(afr[mi][0], afr[mi][1], afr[mi][2], afr[mi][3], addr);
            }
            uint32_t bfr[8][2];
#pragma unroll
            for (int np = 0; np < 4; np++) {
                int nb = wn * 64 + np * 16;
                uint32_t addr = (uint32_t)__cvta_generic_to_shared(
                    &Bs[(nb + b_row) * HSTR + kc + b_c8]);
                LDSM_X4(bfr[2 * np][0], bfr[2 * np][1],
                        bfr[2 * np + 1][0], bfr[2 * np + 1][1], addr);
            }
#pragma unroll
            for (int mi = 0; mi < 2; mi++)
#pragma unroll
                for (int ni = 0; ni < 8; ni++)
                    MMA_F16(acc[mi][ni], afr[mi], bfr[ni]);
        }
        __syncthreads();
    }

    int g = lane >> 2, tq = lane & 3;

    if (ROPE) {
        int n64 = bn + wn * 64;
        int sel = n64 >> 10;             // 0=q, 1=k, 2=v
        int h   = (n64 >> 6) & (HH - 1);
        float* dst = (sel == 0) ? g_q : (sel == 1) ? g_k : g_v;

        if (sel == 2) {
#pragma unroll
            for (int mi = 0; mi < 2; mi++) {
#pragma unroll
                for (int half_ = 0; half_ < 2; half_++) {
                    int row = bm + wm * 32 + mi * 16 + g + half_ * 8;
                    int t = row & (TT - 1), b = row >> 11;
                    float* o = dst + ((size_t)((b * HH + h) * TT + t)) * HD;
#pragma unroll
                    for (int ni = 0; ni < 8; ni++) {
                        int dl = ni * 8 + tq * 2;
                        float2 val;
                        val.x = cvt_tf32(acc[mi][ni][half_ * 2]     + bias[n64 + dl]);
                        val.y = cvt_tf32(acc[mi][ni][half_ * 2 + 1] + bias[n64 + dl + 1]);
                        *(float2*)&o[dl] = val;
                    }
                }
            }
        } else {
            float invf[8];
#pragma unroll
            for (int ni = 0; ni < 4; ni++)
#pragma unroll
                for (int c = 0; c < 2; c++)
                    invf[ni * 2 + c] =
                        exp2f(-(float)(ni * 8 + tq * 2 + c) * 0.4152410118609203f);
#pragma unroll
            for (int mi = 0; mi < 2; mi++) {
#pragma unroll
                for (int half_ = 0; half_ < 2; half_++) {
                    int row = bm + wm * 32 + mi * 16 + g + half_ * 8;
                    int t = row & (TT - 1), b = row >> 11;
                    float* o = dst + ((size_t)((b * HH + h) * TT + t)) * HD;
                    float tf = (float)t;
#pragma unroll
                    for (int ni = 0; ni < 4; ni++) {
#pragma unroll
                        for (int c = 0; c < 2; c++) {
                            int dl = ni * 8 + tq * 2 + c;
                            float v1 = acc[mi][ni][half_ * 2 + c]     + bias[n64 + dl];
                            float v2 = acc[mi][ni + 4][half_ * 2 + c] + bias[n64 + dl + 32];
                            float s, cs;
                            sincosf(tf * invf[ni * 2 + c], &s, &cs);
                            o[dl]      = cvt_tf32(v1 * cs - v2 * s);
                            o[dl + 32] = cvt_tf32(v2 * cs + v1 * s);
                        }
                    }
                }
            }
        }
    } else {
#pragma unroll
        for (int ni = 0; ni < 8; ni++) {
            int col = bn + wn * 64 + ni * 8 + tq * 2;
            float b0 = bias[col], b1 = bias[col + 1];
#pragma unroll
            for (int mi = 0; mi < 2; mi++) {
                int row = bm + wm * 32 + mi * 16 + g;
                float2 lo = make_float2(acc[mi][ni][0] + b0, acc[mi][ni][1] + b1);
                float2 hi = make_float2(acc[mi][ni][2] + b0, acc[mi][ni][3] + b1);
                *(float2*)&C[(size_t)row * Nd + col]       = lo;
                *(float2*)&C[(size_t)(row + 8) * Nd + col] = hi;
            }
        }
    }
}

// ---------------------------------------------------------------------------
// Flash attention (R16: TF32 mma.sync, 2-stage cp.async, 3-way tile class).
// Epilogue now writes fp16 g_att for the fp16 out-projection.
// ---------------------------------------------------------------------------
#define AP 68
#define ATTN_SMEM ((128 * AP + 4 * 64 * AP) * 4)

__global__ __launch_bounds__(256, 2) void flash_attn_mma()
{
    extern __shared__ float sm[];
    float* sQ = sm;                      // [128][AP]
    float* sK = sm + 128 * AP;           // [2][64][AP]
    float* sV = sK + 2 * 64 * AP;        // [2][64][AP]

    int bh = blockIdx.y;
    int qt = (int)gridDim.x - 1 - (int)blockIdx.x;   // heavy tiles first
    int tid = threadIdx.x;
    int warp = tid >> 5, lane = tid & 31;
    int g = lane >> 2, q = lane & 3;

    const float* Qh = g_q + (size_t)bh * TT * HD;
    const float* Kh = g_k + (size_t)bh * TT * HD;
    const float* Vh = g_v + (size_t)bh * TT * HD;

    uint32_t uQ = (uint32_t)__cvta_generic_to_shared(sQ);
    uint32_t uK = (uint32_t)__cvta_generic_to_shared(sK);
    uint32_t uV = (uint32_t)__cvta_generic_to_shared(sV);

    int jm = lane >> 3, lrow = lane & 7;
    int a_row = ((jm & 1) << 3) + lrow, a_col = (jm >> 1) << 2;
    int b_row = ((jm >> 1) << 3) + lrow, b_col = (jm & 1) << 2;

#pragma unroll
    for (int it = 0; it < 8; it++) {
        int slot = tid + it * 256;
        int r = slot >> 4, c4 = (slot & 15) << 2;
        CP_ASYNC16(uQ + (r * AP + c4) * 4,
                   &Qh[(size_t)(qt * 128 + r) * HD + c4]);
    }
#pragma unroll
    for (int it = 0; it < 4; it++) {
        int slot = tid + it * 256;
        int r = slot >> 4, c4 = (slot & 15) << 2;
        CP_ASYNC16(uK + (r * AP + c4) * 4, &Kh[(size_t)r * HD + c4]);
        CP_ASYNC16(uV + (r * AP + c4) * 4, &Vh[(size_t)r * HD + c4]);
    }
    CP_COMMIT();

    float m0 = -1e30f, m1 = -1e30f, l0 = 0.f, l1 = 0.f;
    float oacc[8][4];
#pragma unroll
    for (int ni = 0; ni < 8; ni++)
#pragma unroll
        for (int c = 0; c < 4; c++) oacc[ni][c] = 0.f;

    int wrow = qt * 128 + warp * 16;
    int row0 = wrow + g;
    int row1 = row0 + 8;

    int ktmax = 2 * qt + 1;
    for (int kt = 0; kt <= ktmax; kt++) {
        if (kt > 0) __syncthreads();
        if (kt < ktmax) {
            int ns = (kt + 1) & 1;
            int kb2 = (kt + 1) * 64;
            uint32_t base = (uint32_t)(ns * 64 * AP) * 4;
#pragma unroll
            for (int it = 0; it < 4; it++) {
                int slot = tid + it * 256;
                int r = slot >> 4, c4 = (slot & 15) << 2;
                CP_ASYNC16(uK + base + (r * AP + c4) * 4,
                           &Kh[(size_t)(kb2 + r) * HD + c4]);
                CP_ASYNC16(uV + base + (r * AP + c4) * 4,
                           &Vh[(size_t)(kb2 + r) * HD + c4]);
            }
            CP_COMMIT();
            CP_WAIT(1);
        } else {
            CP_WAIT(0);
        }
        __syncthreads();

        int s = kt & 1;
        int kb = kt * 64;
        const float* sKs = sK + s * 64 * AP;
        const float* sVs = sV + s * 64 * AP;

        if (kb + 63 <= wrow) {
            // FULL path (branch-free)
            float sf[8][4];
#pragma unroll
            for (int ni = 0; ni < 8; ni++)
#pragma unroll
                for (int c = 0; c < 4; c++) sf[ni][c] = 0.f;

#pragma unroll
            for (int kc8 = 0; kc8 < 8; kc8++) {
                int kc = kc8 * 8;
                uint32_t afr[4];
                uint32_t aad = (uint32_t)__cvta_generic_to_shared(
                    &sQ[(warp * 16 + a_row) * AP + kc + a_col]);
                LDSM_X4(afr[0], afr[1], afr[2], afr[3], aad);
                uint32_t bfr[8][2];
#pragma unroll
                for (int np = 0; np < 4; np++) {
                    uint32_t bad = (uint32_t)__cvta_generic_to_shared(
                        &sKs[(np * 16 + b_row) * AP + kc + b_col]);
                    LDSM_X4(bfr[2 * np][0], bfr[2 * np][1],
                            bfr[2 * np + 1][0], bfr[2 * np + 1][1], bad);
                }
#pragma unroll
                for (int ni = 0; ni < 8; ni++)
                    MMA_TF32(sf[ni], afr, bfr[ni]);
            }

            float rmax0 = -1e30f, rmax1 = -1e30f;
#pragma unroll
            for (int ni = 0; ni < 8; ni++) {
                sf[ni][0] *= 0.125f; sf[ni][1] *= 0.125f;
                sf[ni][2] *= 0.125f; sf[ni][3] *= 0.125f;
                rmax0 = fmaxf(rmax0, fmaxf(sf[ni][0], sf[ni][1]));
                rmax1 = fmaxf(rmax1, fmaxf(sf[ni][2], sf[ni][3]));
            }
            rmax0 = fmaxf(rmax0, __shfl_xor_sync(0xffffffffu, rmax0, 1));
            rmax0 = fmaxf(rmax0, __shfl_xor_sync(0xffffffffu, rmax0, 2));
            rmax1 = fmaxf(rmax1, __shfl_xor_sync(0xffffffffu, rmax1, 1));
            rmax1 = fmaxf(rmax1, __shfl_xor_sync(0xffffffffu, rmax1, 2));

            float mn0 = fmaxf(m0, rmax0), mn1 = fmaxf(m1, rmax1);
            float al0 = __expf(m0 - mn0), al1 = __expf(m1 - mn1);
            m0 = mn0; m1 = mn1;

            float rs0 = 0.f, rs1 = 0.f;
#pragma unroll
            for (int ni = 0; ni < 8; ni++) {
                float p0 = cvt_tf32(__expf(sf[ni][0] - mn0));
                float p1 = cvt_tf32(__expf(sf[ni][1] - mn0));
                float p2 = cvt_tf32(__expf(sf[ni][2] - mn1));
                float p3 = cvt_tf32(__expf(sf[ni][3] - mn1));
                sf[ni][0] = p0; sf[ni][1] = p1; sf[ni][2] = p2; sf[ni][3] = p3;
                rs0 += p0 + p1;
                rs1 += p2 + p3;
            }
            rs0 += __shfl_xor_sync(0xffffffffu, rs0, 1);
            rs0 += __shfl_xor_sync(0xffffffffu, rs0, 2);
            rs1 += __shfl_xor_sync(0xffffffffu, rs1, 1);
            rs1 += __shfl_xor_sync(0xffffffffu, rs1, 2);
            l0 = l0 * al0 + rs0;
            l1 = l1 * al1 + rs1;
#pragma unroll
            for (int ni = 0; ni < 8; ni++) {
                oacc[ni][0] *= al0; oacc[ni][1] *= al0;
                oacc[ni][2] *= al1; oacc[ni][3] *= al1;
            }

#pragma unroll
            for (int kc8 = 0; kc8 < 8; kc8++) {
                uint32_t a[4];
                a[0] = __float_as_uint(sf[kc8][0]);
                a[1] = __float_as_uint(sf[kc8][2]);
                a[2] = __float_as_uint(sf[kc8][1]);
                a[3] = __float_as_uint(sf[kc8][3]);
                int cb = kc8 * 8 + 2 * q;
                const float* v0 = &sVs[cb * AP];
                const float* v1 = &sVs[(cb + 1) * AP];
#pragma unroll
                for (int ni = 0; ni < 8; ni++) {
                    int n = ni * 8 + g;
                    uint32_t b[2];
                    b[0] = __float_as_uint(v0[n]);
                    b[1] = __float_as_uint(v1[n]);
                    MMA_TF32(oacc[ni], a, b);
                }
            }
        } else if (kb <= wrow + 15) {
            // DIAGONAL path (masked, block-skip)
            int d = wrow + 15 - kb;
            int ni_max = min((d >> 3) + 1, 8);

            float sf[8][4];
#pragma unroll
            for (int ni = 0; ni < 8; ni++)
#pragma unroll
                for (int c = 0; c < 4; c++) sf[ni][c] = 0.f;

#pragma unroll
            for (int kc8 = 0; kc8 < 8; kc8++) {
                int kc = kc8 * 8;
                uint32_t afr[4];
                uint32_t aad = (uint32_t)__cvta_generic_to_shared(
                    &sQ[(warp * 16 + a_row) * AP + kc + a_col]);
                LDSM_X4(afr[0], afr[1], afr[2], afr[3], aad);
                uint32_t bfr[8][2];
#pragma unroll
                for (int np = 0; np < 4; np++) {
                    uint32_t bad = (uint32_t)__cvta_generic_to_shared(
                        &sKs[(np * 16 + b_row) * AP + kc + b_col]);
                    LDSM_X4(bfr[2 * np][0], bfr[2 * np][1],
                            bfr[2 * np + 1][0], bfr[2 * np + 1][1], bad);
                }
#pragma unroll
                for (int ni = 0; ni < 8; ni++)
                    if (ni < ni_max)
                        MMA_TF32(sf[ni], afr, bfr[ni]);
            }

            float rmax0 = -1e30f, rmax1 = -1e30f;
#pragma unroll
            for (int ni = 0; ni < 8; ni++) {
                if (ni < ni_max) {
                    sf[ni][0] *= 0.125f; sf[ni][1] *= 0.125f;
                    sf[ni][2] *= 0.125f; sf[ni][3] *= 0.125f;
                    int c0 = kb + ni * 8 + 2 * q, c1 = c0 + 1;
                    if (c0 > row0) sf[ni][0] = -1e30f;
                    if (c1 > row0) sf[ni][1] = -1e30f;
                    if (c0 > row1) sf[ni][2] = -1e30f;
                    if (c1 > row1) sf[ni][3] = -1e30f;
                    rmax0 = fmaxf(rmax0, fmaxf(sf[ni][0], sf[ni][1]));
                    rmax1 = fmaxf(rmax1, fmaxf(sf[ni][2], sf[ni][3]));
                }
            }
            rmax0 = fmaxf(rmax0, __shfl_xor_sync(0xffffffffu, rmax0, 1));
            rmax0 = fmaxf(rmax0, __shfl_xor_sync(0xffffffffu, rmax0, 2));
            rmax1 = fmaxf(rmax1, __shfl_xor_sync(0xffffffffu, rmax1, 1));
            rmax1 = fmaxf(rmax1, __shfl_xor_sync(0xffffffffu, rmax1, 2));

            float mn0 = fmaxf(m0, rmax0), mn1 = fmaxf(m1, rmax1);
            float al0 = __expf(m0 - mn0), al1 = __expf(m1 - mn1);
            m0 = mn0; m1 = mn1;

            float rs0 = 0.f, rs1 = 0.f;
#pragma unroll
            for (int ni = 0; ni < 8; ni++) {
                if (ni < ni_max) {
                    float p0 = cvt_tf32(__expf(sf[ni][0] - mn0));
                    float p1 = cvt_tf32(__expf(sf[ni][1] - mn0));
                    float p2 = cvt_tf32(__expf(sf[ni][2] - mn1));
                    float p3 = cvt_tf32(__expf(sf[ni][3] - mn1));
                    sf[ni][0] = p0; sf[ni][1] = p1; sf[ni][2] = p2; sf[ni][3] = p3;
                    rs0 += p0 + p1;
                    rs1 += p2 + p3;
                }
            }
            rs0 += __shfl_xor_sync(0xffffffffu, rs0, 1);
            rs0 += __shfl_xor_sync(0xffffffffu, rs0, 2);
            rs1 += __shfl_xor_sync(0xffffffffu, rs1, 1);
            rs1 += __shfl_xor_sync(0xffffffffu, rs1, 2);
            l0 = l0 * al0 + rs0;
            l1 = l1 * al1 + rs1;
#pragma unroll
            for (int ni = 0; ni < 8; ni++) {
                oacc[ni][0] *= al0; oacc[ni][1] *= al0;
                oacc[ni][2] *= al1; oacc[ni][3] *= al1;
            }

#pragma unroll
            for (int kc8 = 0; kc8 < 8; kc8++) {
                if (kc8 < ni_max) {
                    uint32_t a[4];
                    a[0] = __float_as_uint(sf[kc8][0]);
                    a[1] = __float_as_uint(sf[kc8][2]);
                    a[2] = __float_as_uint(sf[kc8][1]);
                    a[3] = __float_as_uint(sf[kc8][3]);
                    int cb = kc8 * 8 + 2 * q;
                    const float* v0 = &sVs[cb * AP];
                    const float* v1 = &sVs[(cb + 1) * AP];
#pragma unroll
                    for (int ni = 0; ni < 8; ni++) {
                        int n = ni * 8 + g;
                        uint32_t b[2];
                        b[0] = __float_as_uint(v0[n]);
                        b[1] = __float_as_uint(v1[n]);
                        MMA_TF32(oacc[ni], a, b);
                    }
                }
            }
        }
        // else: fully masked tile — contributes exactly 0; skip compute.
    }

    // Epilogue: normalize, write fp16 [B,T,C] (feeds fp16 out-proj)
    float inv0 = 1.0f / l0, inv1 = 1.0f / l1;
    int b_ = bh >> 4, h = bh & 15;
    int trow0 = qt * 128 + warp * 16 + g;
#pragma unroll
    for (int ni = 0; ni < 8; ni++) {
        int col = h * HD + ni * 8 + 2 * q;
        half2 lo = __floats2half2_rn(oacc[ni][0] * inv0, oacc[ni][1] * inv0);
        half2 hi = __floats2half2_rn(oacc[ni][2] * inv1, oacc[ni][3] * inv1);
        *(half2*)&g_att[((size_t)(b_ * TT + trow0)) * CC + col]     = lo;
        *(half2*)&g_att[((size_t)(b_ * TT + trow0 + 8)) * CC + col] = hi;
    }
}

// ---------------------------------------------------------------------------
extern "C" void kernel_launch(void* const* d_in, const int* in_sizes, int n_in,
                              void* d_out, int out_size)
{
    const float* x     = (const float*)d_in[0];
    const float* W_qkv = (const float*)d_in[1];
    const float* b_qkv = (const float*)d_in[2];
    const float* W_out = (const float*)d_in[3];
    const float* b_out = (const float*)d_in[4];
    float* out = (float*)d_out;

    __half *xh, *att, *wqkvT, *woutT;
    cudaGetSymbolAddress((void**)&xh,    g_xh);
    cudaGetSymbolAddress((void**)&att,   g_att);
    cudaGetSymbolAddress((void**)&wqkvT, g_wqkvT);
    cudaGetSymbolAddress((void**)&woutT, g_woutT);

    cudaFuncSetAttribute(f16_gemm<0>,
                         cudaFuncAttributeMaxDynamicSharedMemorySize, GEMM_SMEM);
    cudaFuncSetAttribute(f16_gemm<1>,
                         cudaFuncAttributeMaxDynamicSharedMemorySize, GEMM_SMEM);
    cudaFuncSetAttribute(flash_attn_mma,
                         cudaFuncAttributeMaxDynamicSharedMemorySize, ATTN_SMEM);

    // 0) Fused prologue: weight transposes (fp16) + x rounding (fp16)
    prologue_kernel<<<12288, 256>>>(x, W_qkv, W_out);

    // 1) QKV projection (fp16 MMA) + fused bias/RoPE/head-split epilogue
    f16_gemm<1><<<dim3(NQKV / GBN, MM / GBM), 256, GEMM_SMEM>>>(
        xh, wqkvT, b_qkv, nullptr, NQKV, CC);

    // 2) Causal flash attention (tf32, pipelined K/V, 3-way tile class)
    flash_attn_mma<<<dim3(TT / 128, BB * HH), 256, ATTN_SMEM>>>();

    // 3) Output projection (fp16 MMA)
    f16_gemm<0><<<dim3(CC / GBN, MM / GBM), 256, GEMM_SMEM>>>(
        att, woutT, b_out, out, CC, CC);
}